// round 15
// baseline (speedup 1.0000x reference)
#include <cuda_runtime.h>
#include <cuda_bf16.h>
#include <math.h>

// ---------------- static config ----------------
#define TB 2
#define SS 2048
#define DD 1024
#define HH 16
#define HDD 64
#define ROT 32
#define LQ 512
#define LKV 256
#define FF 1024
#define NR 7
#define CAP 585
#define TT (TB*SS)   // 4096 tokens

#define QC 1536      // q-side concat width: Wq_up(1024) | rot(512)
#define KVC 2560     // kv-side concat width: Wk_up(1024) | Wv_up(1024) | rot(512)

// ---------------- device scratch ----------------
__device__ float g_xn [TT*DD];
__device__ float g_zq [TT*LQ];
__device__ float g_zkv[TT*LKV];
__device__ float g_wqc [LQ*QC];     // Wq_up || packed rot q
__device__ float g_wkvc[LKV*KVC];   // Wk_up || Wv_up || packed rot k
__device__ float g_qc [TT*QC];
__device__ float g_kvc[TT*KVC];
__device__ float g_ao [TT*DD];
__device__ float g_x1 [TT*DD];
__device__ float g_xn2[TT*DD];
__device__ float g_hs [TT*FF];
__device__ float g_aff[TT*NR];
__device__ int2  g_top[TT];
__device__ int   g_selidx[NR*CAP];
__device__ float g_selw  [NR*CAP];
__device__ float g_hr2 [NR*CAP*FF];
__device__ float g_eout[NR*CAP*DD];

// ---------------- helpers ----------------
__device__ __forceinline__ unsigned f2tf32(float f) {
    unsigned u;
    asm("cvt.rna.tf32.f32 %0, %1;" : "=r"(u) : "f"(f));
    return u;
}

__device__ __forceinline__ void mma_tf32(float* c, const unsigned* a, const unsigned* b) {
    asm volatile(
        "mma.sync.aligned.m16n8k8.row.col.f32.tf32.tf32.f32 "
        "{%0,%1,%2,%3}, {%4,%5,%6,%7}, {%8,%9}, {%0,%1,%2,%3};"
        : "+f"(c[0]), "+f"(c[1]), "+f"(c[2]), "+f"(c[3])
        : "r"(a[0]), "r"(a[1]), "r"(a[2]), "r"(a[3]), "r"(b[0]), "r"(b[1]));
}

// ---------------- RMSNorm ----------------
__global__ void rmsnorm_kernel(const float* __restrict__ x,
                               const float* __restrict__ w,
                               float* __restrict__ o) {
    int t = blockIdx.x;
    int tid = threadIdx.x;
    __shared__ float red[256];
    const float4* xr = (const float4*)(x + (long long)t * DD);
    float4 v = xr[tid];
    float ss = v.x*v.x + v.y*v.y + v.z*v.z + v.w*v.w;
    red[tid] = ss; __syncthreads();
    for (int off = 128; off > 0; off >>= 1) {
        if (tid < off) red[tid] += red[tid + off];
        __syncthreads();
    }
    float inv = rsqrtf(red[0] / (float)DD + 1e-6f);
    const float4* wr = (const float4*)w;
    float4 wv = wr[tid];
    float4 ov = make_float4(v.x*inv*wv.x, v.y*inv*wv.y, v.z*inv*wv.z, v.w*inv*wv.w);
    ((float4*)(o + (long long)t * DD))[tid] = ov;
}

// ---------------- SGEMM 128x128x16, 8x8 micro-tile, double-buffered (fp32) --------
// Computes N columns; B has row stride ldb, C row stride ldc (decoupled from N).
__global__ void __launch_bounds__(256)
sgemm128_kernel(const float* __restrict__ A,
                const float* __restrict__ B,
                float* __restrict__ C,
                const float* __restrict__ Add,
                int M, int N, int K, int lda, int ldb, int ldc) {
    int m0 = blockIdx.y * 128, n0 = blockIdx.x * 128;
    int tid = threadIdx.x;
    int ty = tid >> 4, tx = tid & 15;

    __shared__ __align__(16) float As[2][16][128];
    __shared__ __align__(16) float Bs[2][16][128];

    float acc[8][8];
#pragma unroll
    for (int i = 0; i < 8; i++)
#pragma unroll
        for (int j = 0; j < 8; j++) acc[i][j] = 0.f;

    int arow = tid >> 1;
    int acol = (tid & 1) * 8;
    int brow = tid >> 4;
    int bcol = (tid & 15) * 8;
    bool arowok = (m0 + arow) < M;
    const float* Ap = A + (long long)(m0 + arow) * lda + acol;
    const float* Bp = B + (long long)brow * ldb + n0 + bcol;

    float4 av0 = make_float4(0,0,0,0), av1 = av0, bv0, bv1;
    if (arowok) {
        av0 = *(const float4*)&Ap[0];
        av1 = *(const float4*)&Ap[4];
    }
    bv0 = *(const float4*)&Bp[0];
    bv1 = *(const float4*)&Bp[4];

    {
        As[0][acol + 0][arow] = av0.x; As[0][acol + 1][arow] = av0.y;
        As[0][acol + 2][arow] = av0.z; As[0][acol + 3][arow] = av0.w;
        As[0][acol + 4][arow] = av1.x; As[0][acol + 5][arow] = av1.y;
        As[0][acol + 6][arow] = av1.z; As[0][acol + 7][arow] = av1.w;
        *(float4*)&Bs[0][brow][bcol] = bv0;
        *(float4*)&Bs[0][brow][bcol + 4] = bv1;
    }
    __syncthreads();

    int nk = K >> 4;
    for (int t = 0; t < nk; t++) {
        int cur = t & 1;
        if (t + 1 < nk) {
            const float* Apn = Ap + (t + 1) * 16;
            const float* Bpn = Bp + (long long)(t + 1) * 16 * ldb;
            if (arowok) {
                av0 = *(const float4*)&Apn[0];
                av1 = *(const float4*)&Apn[4];
            }
            bv0 = *(const float4*)&Bpn[0];
            bv1 = *(const float4*)&Bpn[4];
        }
#pragma unroll
        for (int kk = 0; kk < 16; kk++) {
            float a[8], b[8];
            *(float4*)&a[0] = *(const float4*)&As[cur][kk][ty * 4];
            *(float4*)&a[4] = *(const float4*)&As[cur][kk][64 + ty * 4];
            *(float4*)&b[0] = *(const float4*)&Bs[cur][kk][tx * 4];
            *(float4*)&b[4] = *(const float4*)&Bs[cur][kk][64 + tx * 4];
#pragma unroll
            for (int i = 0; i < 8; i++)
#pragma unroll
                for (int j = 0; j < 8; j++)
                    acc[i][j] += a[i] * b[j];
        }
        if (t + 1 < nk) {
            int nxt = cur ^ 1;
            As[nxt][acol + 0][arow] = av0.x; As[nxt][acol + 1][arow] = av0.y;
            As[nxt][acol + 2][arow] = av0.z; As[nxt][acol + 3][arow] = av0.w;
            As[nxt][acol + 4][arow] = av1.x; As[nxt][acol + 5][arow] = av1.y;
            As[nxt][acol + 6][arow] = av1.z; As[nxt][acol + 7][arow] = av1.w;
            *(float4*)&Bs[nxt][brow][bcol] = bv0;
            *(float4*)&Bs[nxt][brow][bcol + 4] = bv1;
        }
        __syncthreads();
    }

#pragma unroll
    for (int hi = 0; hi < 2; hi++) {
#pragma unroll
        for (int ii = 0; ii < 4; ii++) {
            int row = m0 + hi * 64 + ty * 4 + ii;
            if (row >= M) continue;
#pragma unroll
            for (int hj = 0; hj < 2; hj++) {
                long long off = (long long)row * ldc + n0 + hj * 64 + tx * 4;
                int ai = hi * 4 + ii;
                float4 r = make_float4(acc[ai][hj*4+0], acc[ai][hj*4+1],
                                       acc[ai][hj*4+2], acc[ai][hj*4+3]);
                if (Add) {
                    float4 ad = *(const float4*)&Add[off];
                    r.x += ad.x; r.y += ad.y; r.z += ad.z; r.w += ad.w;
                }
                *(float4*)&C[off] = r;
            }
        }
    }
}

// ---------------- TF32 tensor-core GEMM 128x128x16 (MoE path) ----------------
// mode 0: C = acc (+Add), B plain.
// mode 1: fused SwiGLU; B halves (a|b) interleaved on the fly; C[M x N/2] = a*silu(b).
// Aidx: optional per-row gather index (row -> Aidx[z*M+row] into A); A not z-offset.
__global__ void __launch_bounds__(256)
tf32gemm_kernel(const float* __restrict__ A,
                const float* __restrict__ B,
                float* __restrict__ C,
                const float* __restrict__ Add,
                const int* __restrict__ Aidx,
                int M, int N, int K,
                long long sA, long long sB, long long sC, int mode) {
    int z = blockIdx.z;
    A += (long long)z * sA;
    B += (long long)z * sB;
    C += (long long)z * sC;
    if (Add) Add += (long long)z * sC;

    const int m0 = blockIdx.y * 128, n0 = blockIdx.x * 128;
    const int tid = threadIdx.x;
    const int w = tid >> 5, lane = tid & 31;
    const int wm = (w >> 2) * 64;
    const int wn = (w & 3) * 32;
    const int gr = lane >> 2, c4 = lane & 3;

    __shared__ float As[2][16][136];
    __shared__ float Bs[2][16][136];

    float acc[4][4][4];
#pragma unroll
    for (int i = 0; i < 4; i++)
#pragma unroll
        for (int j = 0; j < 4; j++)
#pragma unroll
            for (int r = 0; r < 4; r++) acc[i][j][r] = 0.f;

    const int arow = tid >> 1;
    const int acol = (tid & 1) * 8;
    const int brow = tid >> 4;
    const int bcol = (tid & 15) * 8;
    const bool arowok = (m0 + arow) < M;
    long long arow_g = m0 + arow;
    if (Aidx && arowok) arow_g = Aidx[(long long)z * M + m0 + arow];
    const float* Ap = A + arow_g * K + acol;
    const float* BpA;
    const float* BpB = nullptr;
    if (mode == 1) {
        BpA = B + (long long)brow * N + (n0 >> 1) + (bcol >> 1);
        BpB = BpA + FF;
    } else {
        BpA = B + (long long)brow * N + n0 + bcol;
    }

    float ar[8], br[8];
#pragma unroll
    for (int j = 0; j < 8; j++) ar[j] = 0.f;
    if (arowok) {
        float4 a0 = *(const float4*)&Ap[0];
        float4 a1 = *(const float4*)&Ap[4];
        ar[0]=a0.x; ar[1]=a0.y; ar[2]=a0.z; ar[3]=a0.w;
        ar[4]=a1.x; ar[5]=a1.y; ar[6]=a1.z; ar[7]=a1.w;
    }
    {
        float4 b0 = *(const float4*)&BpA[0];
        float4 b1 = (mode == 1) ? *(const float4*)&BpB[0]
                                : *(const float4*)&BpA[4];
        br[0]=b0.x; br[1]=b0.y; br[2]=b0.z; br[3]=b0.w;
        br[4]=b1.x; br[5]=b1.y; br[6]=b1.z; br[7]=b1.w;
    }
#pragma unroll
    for (int j = 0; j < 8; j++)
        As[0][acol + j][arow] = __uint_as_float(f2tf32(ar[j]));
    if (mode == 1) {
#pragma unroll
        for (int i = 0; i < 4; i++) {
            Bs[0][brow][bcol + 2*i]     = __uint_as_float(f2tf32(br[i]));
            Bs[0][brow][bcol + 2*i + 1] = __uint_as_float(f2tf32(br[4 + i]));
        }
    } else {
#pragma unroll
        for (int j = 0; j < 8; j++)
            Bs[0][brow][bcol + j] = __uint_as_float(f2tf32(br[j]));
    }
    __syncthreads();

    const int nk = K >> 4;
    for (int t = 0; t < nk; t++) {
        int cur = t & 1;
        if (t + 1 < nk) {
            const float* Apn = Ap + (t + 1) * 16;
            long long boff = (long long)(t + 1) * 16 * N;
            if (arowok) {
                float4 a0 = *(const float4*)&Apn[0];
                float4 a1 = *(const float4*)&Apn[4];
                ar[0]=a0.x; ar[1]=a0.y; ar[2]=a0.z; ar[3]=a0.w;
                ar[4]=a1.x; ar[5]=a1.y; ar[6]=a1.z; ar[7]=a1.w;
            }
            float4 b0 = *(const float4*)&BpA[boff];
            float4 b1 = (mode == 1) ? *(const float4*)&BpB[boff]
                                    : *(const float4*)&BpA[boff + 4];
            br[0]=b0.x; br[1]=b0.y; br[2]=b0.z; br[3]=b0.w;
            br[4]=b1.x; br[5]=b1.y; br[6]=b1.z; br[7]=b1.w;
        }
#pragma unroll
        for (int ks = 0; ks < 16; ks += 8) {
            unsigned af[4][4], bf[4][2];
#pragma unroll
            for (int mf = 0; mf < 4; mf++) {
                int am = wm + mf * 16;
                af[mf][0] = __float_as_uint(As[cur][ks + c4    ][am + gr    ]);
                af[mf][1] = __float_as_uint(As[cur][ks + c4    ][am + gr + 8]);
                af[mf][2] = __float_as_uint(As[cur][ks + c4 + 4][am + gr    ]);
                af[mf][3] = __float_as_uint(As[cur][ks + c4 + 4][am + gr + 8]);
            }
#pragma unroll
            for (int nf = 0; nf < 4; nf++) {
                int bn = wn + nf * 8;
                bf[nf][0] = __float_as_uint(Bs[cur][ks + c4    ][bn + gr]);
                bf[nf][1] = __float_as_uint(Bs[cur][ks + c4 + 4][bn + gr]);
            }
#pragma unroll
            for (int mf = 0; mf < 4; mf++)
#pragma unroll
                for (int nf = 0; nf < 4; nf++)
                    mma_tf32(acc[mf][nf], af[mf], bf[nf]);
        }
        if (t + 1 < nk) {
            int nxt = cur ^ 1;
#pragma unroll
            for (int j = 0; j < 8; j++)
                As[nxt][acol + j][arow] = __uint_as_float(f2tf32(ar[j]));
            if (mode == 1) {
#pragma unroll
                for (int i = 0; i < 4; i++) {
                    Bs[nxt][brow][bcol + 2*i]     = __uint_as_float(f2tf32(br[i]));
                    Bs[nxt][brow][bcol + 2*i + 1] = __uint_as_float(f2tf32(br[4 + i]));
                }
            } else {
#pragma unroll
                for (int j = 0; j < 8; j++)
                    Bs[nxt][brow][bcol + j] = __uint_as_float(f2tf32(br[j]));
            }
        }
        __syncthreads();
    }

#pragma unroll
    for (int mf = 0; mf < 4; mf++) {
        int rr[2];
        rr[0] = m0 + wm + mf * 16 + gr;
        rr[1] = rr[0] + 8;
#pragma unroll
        for (int nf = 0; nf < 4; nf++) {
            int col = n0 + wn + nf * 8 + c4 * 2;
#pragma unroll
            for (int half = 0; half < 2; half++) {
                int row = rr[half];
                if (row >= M) continue;
                float2 v = make_float2(acc[mf][nf][half*2], acc[mf][nf][half*2+1]);
                if (mode == 0) {
                    if (Add) {
                        float2 ad = *(const float2*)&Add[(long long)row * N + col];
                        v.x += ad.x; v.y += ad.y;
                    }
                    *(float2*)&C[(long long)row * N + col] = v;
                } else {
                    float sw = v.x * (v.y / (1.f + __expf(-v.y)));
                    C[(long long)row * (N >> 1) + (col >> 1)] = sw;
                }
            }
        }
    }
}

// ---------------- weight pack kernels ----------------
__global__ void packq_kernel(const float* __restrict__ Wq_up,
                             const float* __restrict__ Wrot_q) {
    int idx = blockIdx.x * 256 + threadIdx.x;
    if (idx >= LQ * QC) return;
    int r = idx / QC, c = idx % QC;
    if (c < 1024) {
        g_wqc[idx] = Wq_up[r * 1024 + c];
    } else {
        int cc = c - 1024, h = cc >> 5, j = cc & 31;
        g_wqc[idx] = Wrot_q[r * 1024 + h * 64 + j];
    }
}

__global__ void packkv_kernel(const float* __restrict__ Wk_up,
                              const float* __restrict__ Wv_up,
                              const float* __restrict__ Wrot_k) {
    int idx = blockIdx.x * 256 + threadIdx.x;
    if (idx >= LKV * KVC) return;
    int r = idx / KVC, c = idx % KVC;
    if (c < 1024) {
        g_wkvc[idx] = Wk_up[r * 1024 + c];
    } else if (c < 2048) {
        g_wkvc[idx] = Wv_up[r * 1024 + (c - 1024)];
    } else {
        int cc = c - 2048, h = cc >> 5, j = cc & 31;
        g_wkvc[idx] = Wrot_k[r * 1024 + h * 64 + j];
    }
}

// ---------------- RoPE ----------------
__global__ void rope_kernel() {
    int idx = blockIdx.x * blockDim.x + threadIdx.x;
    if (idx >= TT * HH * ROT) return;
    int j = idx & (ROT - 1);
    int h = (idx >> 5) & (HH - 1);
    int t = idx >> 9;
    int s = t & (SS - 1);
    int i = j & 15;
    float invf = __expf(-9.210340371976184f * (float)i / 16.f);
    float ang = (float)s * invf;
    float sn, c;
    sincosf(ang, &sn, &c);
    long long qb = (long long)t * QC + 1024 + h * 32;
    long long kb = (long long)t * KVC + 2048 + h * 32;
    float qr = g_qc[qb + j];
    float kr = g_kvc[kb + j];
    float qo = (j < 16) ? -g_qc[qb + j + 16] : g_qc[qb + j - 16];
    float ko = (j < 16) ? -g_kvc[kb + j + 16] : g_kvc[kb + j - 16];
    g_qc [(long long)t * QC  + h * HDD + 32 + j] = qr * c + qo * sn;
    g_kvc[(long long)t * KVC + h * HDD + 32 + j] = kr * c + ko * sn;
}

// ---------------- flash attention: 128 q x 64 k, 8x4 micro ----------------
__global__ void __launch_bounds__(256)
fattn_kernel(const float* __restrict__ Q, int sq,
             const float* __restrict__ K, int sk,
             const float* __restrict__ V, int sv,
             float* __restrict__ Out, int so) {
    extern __shared__ float sm[];
    float (*Qs)[128] = (float(*)[128])sm;
    float (*Ks)[64]  = (float(*)[64])(sm + 64 * 128);
    float (*Vs)[64]  = (float(*)[64])(sm + 64 * 128 + 64 * 64);
    float (*Ps)[64]  = (float(*)[64])(sm + 64 * 128 + 2 * 64 * 64);

    const int q0 = blockIdx.x * 128;
    const int bh = blockIdx.y;
    const int b = bh >> 4, h = bh & 15;
    const int tid = threadIdx.x;
    const int ty = tid >> 4, tx = tid & 15;

    const float* Qg = Q + (long long)(b * SS + q0) * sq + h * HDD;
    const float* Kg = K + (long long)b * SS * sk + h * HDD;
    const float* Vg = V + (long long)b * SS * sv + h * HDD;

    {
        int r = tid >> 1;
        int c0 = (tid & 1) * 32;
#pragma unroll
        for (int u = 0; u < 8; u++) {
            float4 v = *(const float4*)&Qg[(long long)r * sq + c0 + u * 4];
            Qs[c0 + u*4 + 0][r] = v.x;
            Qs[c0 + u*4 + 1][r] = v.y;
            Qs[c0 + u*4 + 2][r] = v.z;
            Qs[c0 + u*4 + 3][r] = v.w;
        }
    }

    float O[8][4];
#pragma unroll
    for (int i = 0; i < 8; i++)
#pragma unroll
        for (int j = 0; j < 4; j++) O[i][j] = 0.f;
    float m[8], l[8];
#pragma unroll
    for (int i = 0; i < 8; i++) { m[i] = -1e30f; l[i] = 0.f; }

    for (int k0 = 0; k0 < q0 + 128; k0 += 64) {
        __syncthreads();
        {
            int r = tid >> 2;
            int c0 = (tid & 3) * 16;
#pragma unroll
            for (int u = 0; u < 4; u++) {
                float4 kv = *(const float4*)&Kg[(long long)(k0 + r) * sk + c0 + u * 4];
                Ks[c0 + u*4 + 0][r] = kv.x;
                Ks[c0 + u*4 + 1][r] = kv.y;
                Ks[c0 + u*4 + 2][r] = kv.z;
                Ks[c0 + u*4 + 3][r] = kv.w;
                *(float4*)&Vs[r][c0 + u*4] =
                    *(const float4*)&Vg[(long long)(k0 + r) * sv + c0 + u * 4];
            }
        }
        __syncthreads();

        float s[8][4];
#pragma unroll
        for (int i = 0; i < 8; i++)
#pragma unroll
            for (int j = 0; j < 4; j++) s[i][j] = 0.f;
#pragma unroll 8
        for (int d = 0; d < 64; d++) {
            float a[8], bb[4];
            *(float4*)&a[0] = *(const float4*)&Qs[d][ty * 8];
            *(float4*)&a[4] = *(const float4*)&Qs[d][ty * 8 + 4];
            *(float4*)&bb[0] = *(const float4*)&Ks[d][tx * 4];
#pragma unroll
            for (int i = 0; i < 8; i++)
#pragma unroll
                for (int j = 0; j < 4; j++)
                    s[i][j] += a[i] * bb[j];
        }

        if (k0 + 63 > q0) {
#pragma unroll
            for (int i = 0; i < 8; i++)
#pragma unroll
                for (int j = 0; j < 4; j++)
                    s[i][j] = (k0 + tx*4 + j <= q0 + ty*8 + i) ? s[i][j] * 0.125f : -1e30f;
        } else {
#pragma unroll
            for (int i = 0; i < 8; i++)
#pragma unroll
                for (int j = 0; j < 4; j++) s[i][j] *= 0.125f;
        }

#pragma unroll
        for (int i = 0; i < 8; i++) {
            float mx = fmaxf(fmaxf(s[i][0], s[i][1]), fmaxf(s[i][2], s[i][3]));
#pragma unroll
            for (int off = 1; off < 16; off <<= 1)
                mx = fmaxf(mx, __shfl_xor_sync(0xffffffffu, mx, off));
            float mn = fmaxf(m[i], mx);
            float corr = __expf(m[i] - mn);
            float p0 = __expf(s[i][0] - mn);
            float p1 = __expf(s[i][1] - mn);
            float p2 = __expf(s[i][2] - mn);
            float p3 = __expf(s[i][3] - mn);
            *(float4*)&Ps[ty*8 + i][tx*4] = make_float4(p0, p1, p2, p3);
            float sum = p0 + p1 + p2 + p3;
#pragma unroll
            for (int off = 1; off < 16; off <<= 1)
                sum += __shfl_xor_sync(0xffffffffu, sum, off);
            l[i] = l[i] * corr + sum;
            m[i] = mn;
            O[i][0] *= corr; O[i][1] *= corr; O[i][2] *= corr; O[i][3] *= corr;
        }
        __syncthreads();

#pragma unroll 8
        for (int c = 0; c < 64; c++) {
            float bb[4];
            *(float4*)&bb[0] = *(const float4*)&Vs[c][tx * 4];
#pragma unroll
            for (int i = 0; i < 8; i++) {
                float a = Ps[ty*8 + i][c];
                O[i][0] += a*bb[0]; O[i][1] += a*bb[1];
                O[i][2] += a*bb[2]; O[i][3] += a*bb[3];
            }
        }
    }

    float* Og = Out + (long long)(b * SS + q0) * so + h * HDD;
#pragma unroll
    for (int i = 0; i < 8; i++) {
        float inv = 1.f / l[i];
        float4 o = make_float4(O[i][0]*inv, O[i][1]*inv, O[i][2]*inv, O[i][3]*inv);
        *(float4*)&Og[(long long)(ty*8 + i) * so + tx * 4] = o;
    }
}

// ---------------- gating ----------------
__global__ void gate_kernel(const float* __restrict__ Wg,
                            const float* __restrict__ bias) {
    int t = blockIdx.x;
    int w = threadIdx.x >> 5, lane = threadIdx.x & 31;
    if (w >= NR) return;
    float s = 0.f;
    const float* xr = g_xn2 + (long long)t * DD;
    for (int i = lane; i < DD; i += 32) s += xr[i] * Wg[i * NR + w];
#pragma unroll
    for (int off = 16; off > 0; off >>= 1)
        s += __shfl_down_sync(0xffffffff, s, off);
    if (lane == 0)
        g_aff[t * NR + w] = 1.f / (1.f + __expf(-(s + bias[w])));
}

// ---------------- per-token top-2 ----------------
__global__ void top2_kernel() {
    int t = blockIdx.x * blockDim.x + threadIdx.x;
    if (t >= TT) return;
    float a[NR];
#pragma unroll
    for (int e = 0; e < NR; e++) a[e] = g_aff[t * NR + e];
    int e1 = 0; float b1 = a[0];
#pragma unroll
    for (int e = 1; e < NR; e++) if (a[e] > b1) { b1 = a[e]; e1 = e; }
    int e2 = -1; float b2 = -1.f;
#pragma unroll
    for (int e = 0; e < NR; e++) if (e != e1 && a[e] > b2) { b2 = a[e]; e2 = e; }
    g_top[t] = make_int2(e1, e2);
}

// ---------------- per-expert capacity selection ----------------
__global__ void select_kernel() {
    __shared__ unsigned long long keys[TT];
    int e = blockIdx.x;
    int tid = threadIdx.x;
    for (int i = tid; i < TT; i += 1024) {
        int2 tp = g_top[i];
        unsigned hi;
        if (tp.x == e || tp.y == e) {
            unsigned ev = __float_as_uint(g_aff[i * NR + e]);
            hi = ~ev;
        } else {
            hi = 0xFFFFFFFFu;
        }
        keys[i] = ((unsigned long long)hi << 32) | (unsigned)i;
    }
    __syncthreads();
    for (int ksz = 2; ksz <= TT; ksz <<= 1) {
        for (int j = ksz >> 1; j > 0; j >>= 1) {
            for (int base = tid; base < TT / 2; base += 1024) {
                int i = ((base & ~(j - 1)) << 1) | (base & (j - 1));
                int p = i + j;
                bool up = ((i & ksz) == 0);
                unsigned long long a = keys[i], b2 = keys[p];
                if ((a > b2) == up) { keys[i] = b2; keys[p] = a; }
            }
            __syncthreads();
        }
    }
    for (int c = tid; c < CAP; c += 1024) {
        unsigned long long kk = keys[c];
        int idx = (int)(kk & 0xFFFFFFFFu);
        bool valid = (unsigned)(kk >> 32) != 0xFFFFFFFFu;
        g_selidx[e * CAP + c] = idx;
        g_selw[e * CAP + c] = valid ? g_aff[idx * NR + e] : 0.f;
    }
}

// ---------------- scatter-add ----------------
__global__ void scatter_kernel(float* __restrict__ out) {
    int row = blockIdx.x;
    float w = g_selw[row];
    if (w == 0.f) return;
    int t = g_selidx[row];
    int i = threadIdx.x * 4;
    const float* src = &g_eout[(long long)row * DD + i];
    float* dst = &out[(long long)t * DD + i];
#pragma unroll
    for (int j = 0; j < 4; j++) atomicAdd(dst + j, src[j] * w);
}

// ---------------- host helpers ----------------
static float* sym(const void* s) {
    void* p = nullptr;
    cudaGetSymbolAddress(&p, (const void*)s);
    return (float*)p;
}

static void run_gemm(cudaStream_t st, const float* A, const float* B, float* C,
                     const float* Add, int M, int N, int K,
                     int lda, int ldb, int ldc) {
    dim3 grid((N + 127) / 128, (M + 127) / 128);
    sgemm128_kernel<<<grid, 256, 0, st>>>(A, B, C, Add, M, N, K, lda, ldb, ldc);
}

static void run_tf32(cudaStream_t st, const float* A, const float* B, float* C,
                     const float* Add, const int* Aidx, int M, int N, int K, int batch,
                     long long sA, long long sB, long long sC, int mode) {
    dim3 grid(N / 128, (M + 127) / 128, batch);
    tf32gemm_kernel<<<grid, 256, 0, st>>>(A, B, C, Add, Aidx, M, N, K, sA, sB, sC, mode);
}

#define ATT_SMEM (98304)

// one-time-created stream/event resources (work per call is identical/deterministic)
static cudaStream_t g_s1;
static cudaEvent_t g_eStart, g_eXN, g_ePQ, g_eZQ, g_eKV, g_eR, g_eMoE;
static int g_res_init = 0;

extern "C" void kernel_launch(void* const* d_in, const int* in_sizes, int n_in,
                              void* d_out, int out_size) {
    const float* x       = (const float*)d_in[0];
    const float* Wq_lat  = (const float*)d_in[2];
    const float* Wkv_lat = (const float*)d_in[3];
    const float* Wrot_q  = (const float*)d_in[4];
    const float* Wrot_k  = (const float*)d_in[5];
    const float* Wq_up   = (const float*)d_in[6];
    const float* Wk_up   = (const float*)d_in[7];
    const float* Wv_up   = (const float*)d_in[8];
    const float* Wout    = (const float*)d_in[9];
    const float* n1w     = (const float*)d_in[10];
    const float* n2w     = (const float*)d_in[11];
    const float* Ws1     = (const float*)d_in[12];
    const float* Ws2     = (const float*)d_in[13];
    const float* Wr1     = (const float*)d_in[14];
    const float* Wr2     = (const float*)d_in[15];
    const float* Wgate   = (const float*)d_in[16];
    const float* ebias   = (const float*)d_in[17];
    float* out = (float*)d_out;

    float* p_xn   = sym(&g_xn);
    float* p_zq   = sym(&g_zq);
    float* p_zkv  = sym(&g_zkv);
    float* p_wqc  = sym(&g_wqc);
    float* p_wkvc = sym(&g_wkvc);
    float* p_qc   = sym(&g_qc);
    float* p_kvc  = sym(&g_kvc);
    float* p_ao   = sym(&g_ao);
    float* p_x1   = sym(&g_x1);
    float* p_xn2  = sym(&g_xn2);
    float* p_hs   = sym(&g_hs);
    float* p_hr2  = sym(&g_hr2);
    float* p_eo   = sym(&g_eout);
    int*   p_sel  = (int*)sym(&g_selidx);

    if (!g_res_init) {
        cudaFuncSetAttribute(fattn_kernel, cudaFuncAttributeMaxDynamicSharedMemorySize,
                             ATT_SMEM);
        cudaStreamCreateWithFlags(&g_s1, cudaStreamNonBlocking);
        cudaEventCreateWithFlags(&g_eStart, cudaEventDisableTiming);
        cudaEventCreateWithFlags(&g_eXN, cudaEventDisableTiming);
        cudaEventCreateWithFlags(&g_ePQ, cudaEventDisableTiming);
        cudaEventCreateWithFlags(&g_eZQ, cudaEventDisableTiming);
        cudaEventCreateWithFlags(&g_eKV, cudaEventDisableTiming);
        cudaEventCreateWithFlags(&g_eR, cudaEventDisableTiming);
        cudaEventCreateWithFlags(&g_eMoE, cudaEventDisableTiming);
        g_res_init = 1;
    }
    cudaStream_t s0 = 0, s1 = g_s1;

    // fork
    cudaEventRecord(g_eStart, s0);
    cudaStreamWaitEvent(s1, g_eStart, 0);

    // s0: rmsnorm; s1: weight packs (both tiny, concurrent)
    rmsnorm_kernel<<<TT, 256, 0, s0>>>(x, n1w, p_xn);
    cudaEventRecord(g_eXN, s0);
    packq_kernel <<<(LQ * QC + 255) / 256, 256, 0, s1>>>(Wq_up, Wrot_q);
    packkv_kernel<<<(LKV * KVC + 255) / 256, 256, 0, s1>>>(Wk_up, Wv_up, Wrot_k);
    cudaEventRecord(g_ePQ, s1);

    // s0 q chain: zq = xn@Wq_lat, then qc_up (N=1024 slice of wqc)
    run_gemm(s0, p_xn, Wq_lat, p_zq, nullptr, TT, LQ, DD, DD, LQ, LQ);
    cudaEventRecord(g_eZQ, s0);
    cudaStreamWaitEvent(s0, g_ePQ, 0);
    run_gemm(s0, p_zq, p_wqc, p_qc, nullptr, TT, 1024, LQ, LQ, QC, QC);

    // s1 kv chain: zkv -> kvc, then qc_rot (N=512 slice, needs zq)
    cudaStreamWaitEvent(s1, g_eXN, 0);
    run_gemm(s1, p_xn, Wkv_lat, p_zkv, nullptr, TT, LKV, DD, DD, LKV, LKV);
    run_gemm(s1, p_zkv, p_wkvc, p_kvc, nullptr, TT, KVC, LKV, LKV, KVC, KVC);
    cudaStreamWaitEvent(s1, g_eZQ, 0);
    run_gemm(s1, p_zq, p_wqc + 1024, p_qc + 1024, nullptr, TT, 512, LQ, LQ, QC, QC);
    cudaEventRecord(g_eKV, s1);
    cudaStreamWaitEvent(s0, g_eKV, 0);

    rope_kernel<<<(TT * HH * ROT + 255) / 256, 256, 0, s0>>>();
    fattn_kernel<<<dim3(SS / 128, TB * HH), 256, ATT_SMEM, s0>>>(
        p_qc, QC, p_kvc, KVC, p_kvc + 1024, KVC, p_ao, DD);
    run_gemm(s0, p_ao, Wout, p_x1, x, TT, DD, DD, DD, DD, DD);
    rmsnorm_kernel<<<TT, 256, 0, s0>>>(p_x1, n2w, p_xn2);
    cudaEventRecord(g_eR, s0);
    cudaStreamWaitEvent(s1, g_eR, 0);

    // routed chain on s1 (gather fused into Wr1 A-loader via selidx)
    gate_kernel<<<TT, 256, 0, s1>>>(Wgate, ebias);
    top2_kernel<<<(TT + 255) / 256, 256, 0, s1>>>();
    select_kernel<<<NR, 1024, 0, s1>>>();
    run_tf32(s1, p_xn2, Wr1, p_hr2, nullptr, p_sel, CAP, 2 * FF, DD, NR,
             0, (long long)DD * 2 * FF, (long long)CAP * FF, 1);
    run_tf32(s1, p_hr2, Wr2, p_eo, nullptr, nullptr, CAP, DD, FF, NR,
             (long long)CAP * FF, (long long)FF * DD, (long long)CAP * DD, 0);
    cudaEventRecord(g_eMoE, s1);

    // shared chain on main: out = x1 + shared (Add-epilogue)
    run_tf32(s0, p_xn2, Ws1, p_hs, nullptr, nullptr, TT, 2 * FF, DD, 1, 0, 0,
             (long long)TT * FF, 1);
    run_tf32(s0, p_hs, Ws2, out, p_x1, nullptr, TT, DD, FF, 1, 0, 0, 0, 0);

    // join: scatter routed experts into out
    cudaStreamWaitEvent(s0, g_eMoE, 0);
    scatter_kernel<<<NR * CAP, 256, 0, s0>>>(out);
}

// round 16
// speedup vs baseline: 1.0195x; 1.0195x over previous
#include <cuda_runtime.h>
#include <cuda_bf16.h>
#include <math.h>

// ---------------- static config ----------------
#define TB 2
#define SS 2048
#define DD 1024
#define HH 16
#define HDD 64
#define ROT 32
#define LQ 512
#define LKV 256
#define FF 1024
#define NR 7
#define CAP 585
#define TT (TB*SS)   // 4096 tokens

#define QC 1536      // q-side concat width: Wq_up(1024) | rot(512)
#define KVC 2560     // kv-side concat width: Wk_up(1024) | Wv_up(1024) | rot(512)

// ---------------- device scratch ----------------
__device__ float g_xn [TT*DD];
__device__ float g_zq [TT*LQ];
__device__ float g_zkv[TT*LKV];
__device__ float g_wqc [LQ*QC];     // Wq_up || packed rot q
__device__ float g_wkvc[LKV*KVC];   // Wk_up || Wv_up || packed rot k
__device__ float g_qc [TT*QC];
__device__ float g_kvc[TT*KVC];
__device__ float g_ao [TT*DD];
__device__ float g_x1 [TT*DD];
__device__ float g_xn2[TT*DD];
__device__ float g_hs [TT*FF];
__device__ float g_aff[TT*NR];
__device__ int2  g_top[TT];
__device__ int   g_selidx[NR*CAP];
__device__ float g_selw  [NR*CAP];
__device__ float g_hr2 [NR*CAP*FF];
__device__ float g_eout[NR*CAP*DD];

// ---------------- helpers ----------------
__device__ __forceinline__ unsigned f2tf32(float f) {
    unsigned u;
    asm("cvt.rna.tf32.f32 %0, %1;" : "=r"(u) : "f"(f));
    return u;
}

__device__ __forceinline__ void mma_tf32(float* c, const unsigned* a, const unsigned* b) {
    asm volatile(
        "mma.sync.aligned.m16n8k8.row.col.f32.tf32.tf32.f32 "
        "{%0,%1,%2,%3}, {%4,%5,%6,%7}, {%8,%9}, {%0,%1,%2,%3};"
        : "+f"(c[0]), "+f"(c[1]), "+f"(c[2]), "+f"(c[3])
        : "r"(a[0]), "r"(a[1]), "r"(a[2]), "r"(a[3]), "r"(b[0]), "r"(b[1]));
}

// ---------------- RMSNorm ----------------
__global__ void rmsnorm_kernel(const float* __restrict__ x,
                               const float* __restrict__ w,
                               float* __restrict__ o) {
    int t = blockIdx.x;
    int tid = threadIdx.x;
    __shared__ float red[256];
    const float4* xr = (const float4*)(x + (long long)t * DD);
    float4 v = xr[tid];
    float ss = v.x*v.x + v.y*v.y + v.z*v.z + v.w*v.w;
    red[tid] = ss; __syncthreads();
    for (int off = 128; off > 0; off >>= 1) {
        if (tid < off) red[tid] += red[tid + off];
        __syncthreads();
    }
    float inv = rsqrtf(red[0] / (float)DD + 1e-6f);
    const float4* wr = (const float4*)w;
    float4 wv = wr[tid];
    float4 ov = make_float4(v.x*inv*wv.x, v.y*inv*wv.y, v.z*inv*wv.z, v.w*inv*wv.w);
    ((float4*)(o + (long long)t * DD))[tid] = ov;
}

// ---------------- SGEMM 128x128x16, 8x8 micro-tile, double-buffered (fp32) ----------------
__global__ void __launch_bounds__(256)
sgemm128_kernel(const float* __restrict__ A,
                const float* __restrict__ B,
                float* __restrict__ C,
                const float* __restrict__ Add,
                int M, int N, int K, int lda) {
    int m0 = blockIdx.y * 128, n0 = blockIdx.x * 128;
    int tid = threadIdx.x;
    int ty = tid >> 4, tx = tid & 15;

    __shared__ __align__(16) float As[2][16][128];
    __shared__ __align__(16) float Bs[2][16][128];

    float acc[8][8];
#pragma unroll
    for (int i = 0; i < 8; i++)
#pragma unroll
        for (int j = 0; j < 8; j++) acc[i][j] = 0.f;

    int arow = tid >> 1;
    int acol = (tid & 1) * 8;
    int brow = tid >> 4;
    int bcol = (tid & 15) * 8;
    bool arowok = (m0 + arow) < M;
    const float* Ap = A + (long long)(m0 + arow) * lda + acol;
    const float* Bp = B + (long long)brow * N + n0 + bcol;

    float4 av0 = make_float4(0,0,0,0), av1 = av0, bv0, bv1;
    if (arowok) {
        av0 = *(const float4*)&Ap[0];
        av1 = *(const float4*)&Ap[4];
    }
    bv0 = *(const float4*)&Bp[0];
    bv1 = *(const float4*)&Bp[4];

    {
        As[0][acol + 0][arow] = av0.x; As[0][acol + 1][arow] = av0.y;
        As[0][acol + 2][arow] = av0.z; As[0][acol + 3][arow] = av0.w;
        As[0][acol + 4][arow] = av1.x; As[0][acol + 5][arow] = av1.y;
        As[0][acol + 6][arow] = av1.z; As[0][acol + 7][arow] = av1.w;
        *(float4*)&Bs[0][brow][bcol] = bv0;
        *(float4*)&Bs[0][brow][bcol + 4] = bv1;
    }
    __syncthreads();

    int nk = K >> 4;
    for (int t = 0; t < nk; t++) {
        int cur = t & 1;
        if (t + 1 < nk) {
            const float* Apn = Ap + (t + 1) * 16;
            const float* Bpn = Bp + (long long)(t + 1) * 16 * N;
            if (arowok) {
                av0 = *(const float4*)&Apn[0];
                av1 = *(const float4*)&Apn[4];
            }
            bv0 = *(const float4*)&Bpn[0];
            bv1 = *(const float4*)&Bpn[4];
        }
#pragma unroll
        for (int kk = 0; kk < 16; kk++) {
            float a[8], b[8];
            *(float4*)&a[0] = *(const float4*)&As[cur][kk][ty * 4];
            *(float4*)&a[4] = *(const float4*)&As[cur][kk][64 + ty * 4];
            *(float4*)&b[0] = *(const float4*)&Bs[cur][kk][tx * 4];
            *(float4*)&b[4] = *(const float4*)&Bs[cur][kk][64 + tx * 4];
#pragma unroll
            for (int i = 0; i < 8; i++)
#pragma unroll
                for (int j = 0; j < 8; j++)
                    acc[i][j] += a[i] * b[j];
        }
        if (t + 1 < nk) {
            int nxt = cur ^ 1;
            As[nxt][acol + 0][arow] = av0.x; As[nxt][acol + 1][arow] = av0.y;
            As[nxt][acol + 2][arow] = av0.z; As[nxt][acol + 3][arow] = av0.w;
            As[nxt][acol + 4][arow] = av1.x; As[nxt][acol + 5][arow] = av1.y;
            As[nxt][acol + 6][arow] = av1.z; As[nxt][acol + 7][arow] = av1.w;
            *(float4*)&Bs[nxt][brow][bcol] = bv0;
            *(float4*)&Bs[nxt][brow][bcol + 4] = bv1;
        }
        __syncthreads();
    }

#pragma unroll
    for (int hi = 0; hi < 2; hi++) {
#pragma unroll
        for (int ii = 0; ii < 4; ii++) {
            int row = m0 + hi * 64 + ty * 4 + ii;
            if (row >= M) continue;
#pragma unroll
            for (int hj = 0; hj < 2; hj++) {
                long long off = (long long)row * N + n0 + hj * 64 + tx * 4;
                int ai = hi * 4 + ii;
                float4 r = make_float4(acc[ai][hj*4+0], acc[ai][hj*4+1],
                                       acc[ai][hj*4+2], acc[ai][hj*4+3]);
                if (Add) {
                    float4 ad = *(const float4*)&Add[off];
                    r.x += ad.x; r.y += ad.y; r.z += ad.z; r.w += ad.w;
                }
                *(float4*)&C[off] = r;
            }
        }
    }
}

// ---------------- TF32 tensor-core GEMM 128x128x16 (MoE path) ----------------
// mode 0: C = acc (+Add), B plain.
// mode 1: fused SwiGLU; B halves (a|b) interleaved on the fly; C[M x N/2] = a*silu(b).
// Aidx: optional per-row gather index (row -> Aidx[z*M+row] into A); A not z-offset.
__global__ void __launch_bounds__(256)
tf32gemm_kernel(const float* __restrict__ A,
                const float* __restrict__ B,
                float* __restrict__ C,
                const float* __restrict__ Add,
                const int* __restrict__ Aidx,
                int M, int N, int K,
                long long sA, long long sB, long long sC, int mode) {
    int z = blockIdx.z;
    A += (long long)z * sA;
    B += (long long)z * sB;
    C += (long long)z * sC;
    if (Add) Add += (long long)z * sC;

    const int m0 = blockIdx.y * 128, n0 = blockIdx.x * 128;
    const int tid = threadIdx.x;
    const int w = tid >> 5, lane = tid & 31;
    const int wm = (w >> 2) * 64;
    const int wn = (w & 3) * 32;
    const int gr = lane >> 2, c4 = lane & 3;

    __shared__ float As[2][16][136];
    __shared__ float Bs[2][16][136];

    float acc[4][4][4];
#pragma unroll
    for (int i = 0; i < 4; i++)
#pragma unroll
        for (int j = 0; j < 4; j++)
#pragma unroll
            for (int r = 0; r < 4; r++) acc[i][j][r] = 0.f;

    const int arow = tid >> 1;
    const int acol = (tid & 1) * 8;
    const int brow = tid >> 4;
    const int bcol = (tid & 15) * 8;
    const bool arowok = (m0 + arow) < M;
    long long arow_g = m0 + arow;
    if (Aidx && arowok) arow_g = Aidx[(long long)z * M + m0 + arow];
    const float* Ap = A + arow_g * K + acol;
    const float* BpA;
    const float* BpB = nullptr;
    if (mode == 1) {
        BpA = B + (long long)brow * N + (n0 >> 1) + (bcol >> 1);
        BpB = BpA + FF;
    } else {
        BpA = B + (long long)brow * N + n0 + bcol;
    }

    float ar[8], br[8];
#pragma unroll
    for (int j = 0; j < 8; j++) ar[j] = 0.f;
    if (arowok) {
        float4 a0 = *(const float4*)&Ap[0];
        float4 a1 = *(const float4*)&Ap[4];
        ar[0]=a0.x; ar[1]=a0.y; ar[2]=a0.z; ar[3]=a0.w;
        ar[4]=a1.x; ar[5]=a1.y; ar[6]=a1.z; ar[7]=a1.w;
    }
    {
        float4 b0 = *(const float4*)&BpA[0];
        float4 b1 = (mode == 1) ? *(const float4*)&BpB[0]
                                : *(const float4*)&BpA[4];
        br[0]=b0.x; br[1]=b0.y; br[2]=b0.z; br[3]=b0.w;
        br[4]=b1.x; br[5]=b1.y; br[6]=b1.z; br[7]=b1.w;
    }
#pragma unroll
    for (int j = 0; j < 8; j++)
        As[0][acol + j][arow] = __uint_as_float(f2tf32(ar[j]));
    if (mode == 1) {
#pragma unroll
        for (int i = 0; i < 4; i++) {
            Bs[0][brow][bcol + 2*i]     = __uint_as_float(f2tf32(br[i]));
            Bs[0][brow][bcol + 2*i + 1] = __uint_as_float(f2tf32(br[4 + i]));
        }
    } else {
#pragma unroll
        for (int j = 0; j < 8; j++)
            Bs[0][brow][bcol + j] = __uint_as_float(f2tf32(br[j]));
    }
    __syncthreads();

    const int nk = K >> 4;
    for (int t = 0; t < nk; t++) {
        int cur = t & 1;
        if (t + 1 < nk) {
            const float* Apn = Ap + (t + 1) * 16;
            long long boff = (long long)(t + 1) * 16 * N;
            if (arowok) {
                float4 a0 = *(const float4*)&Apn[0];
                float4 a1 = *(const float4*)&Apn[4];
                ar[0]=a0.x; ar[1]=a0.y; ar[2]=a0.z; ar[3]=a0.w;
                ar[4]=a1.x; ar[5]=a1.y; ar[6]=a1.z; ar[7]=a1.w;
            }
            float4 b0 = *(const float4*)&BpA[boff];
            float4 b1 = (mode == 1) ? *(const float4*)&BpB[boff]
                                    : *(const float4*)&BpA[boff + 4];
            br[0]=b0.x; br[1]=b0.y; br[2]=b0.z; br[3]=b0.w;
            br[4]=b1.x; br[5]=b1.y; br[6]=b1.z; br[7]=b1.w;
        }
#pragma unroll
        for (int ks = 0; ks < 16; ks += 8) {
            unsigned af[4][4], bf[4][2];
#pragma unroll
            for (int mf = 0; mf < 4; mf++) {
                int am = wm + mf * 16;
                af[mf][0] = __float_as_uint(As[cur][ks + c4    ][am + gr    ]);
                af[mf][1] = __float_as_uint(As[cur][ks + c4    ][am + gr + 8]);
                af[mf][2] = __float_as_uint(As[cur][ks + c4 + 4][am + gr    ]);
                af[mf][3] = __float_as_uint(As[cur][ks + c4 + 4][am + gr + 8]);
            }
#pragma unroll
            for (int nf = 0; nf < 4; nf++) {
                int bn = wn + nf * 8;
                bf[nf][0] = __float_as_uint(Bs[cur][ks + c4    ][bn + gr]);
                bf[nf][1] = __float_as_uint(Bs[cur][ks + c4 + 4][bn + gr]);
            }
#pragma unroll
            for (int mf = 0; mf < 4; mf++)
#pragma unroll
                for (int nf = 0; nf < 4; nf++)
                    mma_tf32(acc[mf][nf], af[mf], bf[nf]);
        }
        if (t + 1 < nk) {
            int nxt = cur ^ 1;
#pragma unroll
            for (int j = 0; j < 8; j++)
                As[nxt][acol + j][arow] = __uint_as_float(f2tf32(ar[j]));
            if (mode == 1) {
#pragma unroll
                for (int i = 0; i < 4; i++) {
                    Bs[nxt][brow][bcol + 2*i]     = __uint_as_float(f2tf32(br[i]));
                    Bs[nxt][brow][bcol + 2*i + 1] = __uint_as_float(f2tf32(br[4 + i]));
                }
            } else {
#pragma unroll
                for (int j = 0; j < 8; j++)
                    Bs[nxt][brow][bcol + j] = __uint_as_float(f2tf32(br[j]));
            }
        }
        __syncthreads();
    }

#pragma unroll
    for (int mf = 0; mf < 4; mf++) {
        int rr[2];
        rr[0] = m0 + wm + mf * 16 + gr;
        rr[1] = rr[0] + 8;
#pragma unroll
        for (int nf = 0; nf < 4; nf++) {
            int col = n0 + wn + nf * 8 + c4 * 2;
#pragma unroll
            for (int half = 0; half < 2; half++) {
                int row = rr[half];
                if (row >= M) continue;
                float2 v = make_float2(acc[mf][nf][half*2], acc[mf][nf][half*2+1]);
                if (mode == 0) {
                    if (Add) {
                        float2 ad = *(const float2*)&Add[(long long)row * N + col];
                        v.x += ad.x; v.y += ad.y;
                    }
                    *(float2*)&C[(long long)row * N + col] = v;
                } else {
                    float sw = v.x * (v.y / (1.f + __expf(-v.y)));
                    C[(long long)row * (N >> 1) + (col >> 1)] = sw;
                }
            }
        }
    }
}

// ---------------- weight pack kernels ----------------
__global__ void packq_kernel(const float* __restrict__ Wq_up,
                             const float* __restrict__ Wrot_q) {
    int idx = blockIdx.x * 256 + threadIdx.x;
    if (idx >= LQ * QC) return;
    int r = idx / QC, c = idx % QC;
    if (c < 1024) {
        g_wqc[idx] = Wq_up[r * 1024 + c];
    } else {
        int cc = c - 1024, h = cc >> 5, j = cc & 31;
        g_wqc[idx] = Wrot_q[r * 1024 + h * 64 + j];
    }
}

__global__ void packkv_kernel(const float* __restrict__ Wk_up,
                              const float* __restrict__ Wv_up,
                              const float* __restrict__ Wrot_k) {
    int idx = blockIdx.x * 256 + threadIdx.x;
    if (idx >= LKV * KVC) return;
    int r = idx / KVC, c = idx % KVC;
    if (c < 1024) {
        g_wkvc[idx] = Wk_up[r * 1024 + c];
    } else if (c < 2048) {
        g_wkvc[idx] = Wv_up[r * 1024 + (c - 1024)];
    } else {
        int cc = c - 2048, h = cc >> 5, j = cc & 31;
        g_wkvc[idx] = Wrot_k[r * 1024 + h * 64 + j];
    }
}

// ---------------- RoPE ----------------
__global__ void rope_kernel() {
    int idx = blockIdx.x * blockDim.x + threadIdx.x;
    if (idx >= TT * HH * ROT) return;
    int j = idx & (ROT - 1);
    int h = (idx >> 5) & (HH - 1);
    int t = idx >> 9;
    int s = t & (SS - 1);
    int i = j & 15;
    float invf = __expf(-9.210340371976184f * (float)i / 16.f);
    float ang = (float)s * invf;
    float sn, c;
    sincosf(ang, &sn, &c);
    long long qb = (long long)t * QC + 1024 + h * 32;
    long long kb = (long long)t * KVC + 2048 + h * 32;
    float qr = g_qc[qb + j];
    float kr = g_kvc[kb + j];
    float qo = (j < 16) ? -g_qc[qb + j + 16] : g_qc[qb + j - 16];
    float ko = (j < 16) ? -g_kvc[kb + j + 16] : g_kvc[kb + j - 16];
    g_qc [(long long)t * QC  + h * HDD + 32 + j] = qr * c + qo * sn;
    g_kvc[(long long)t * KVC + h * HDD + 32 + j] = kr * c + ko * sn;
}

// ---------------- flash attention: 128 q x 64 k, 8x4 micro ----------------
__global__ void __launch_bounds__(256)
fattn_kernel(const float* __restrict__ Q, int sq,
             const float* __restrict__ K, int sk,
             const float* __restrict__ V, int sv,
             float* __restrict__ Out, int so) {
    extern __shared__ float sm[];
    float (*Qs)[128] = (float(*)[128])sm;
    float (*Ks)[64]  = (float(*)[64])(sm + 64 * 128);
    float (*Vs)[64]  = (float(*)[64])(sm + 64 * 128 + 64 * 64);
    float (*Ps)[64]  = (float(*)[64])(sm + 64 * 128 + 2 * 64 * 64);

    const int q0 = blockIdx.x * 128;
    const int bh = blockIdx.y;
    const int b = bh >> 4, h = bh & 15;
    const int tid = threadIdx.x;
    const int ty = tid >> 4, tx = tid & 15;

    const float* Qg = Q + (long long)(b * SS + q0) * sq + h * HDD;
    const float* Kg = K + (long long)b * SS * sk + h * HDD;
    const float* Vg = V + (long long)b * SS * sv + h * HDD;

    {
        int r = tid >> 1;
        int c0 = (tid & 1) * 32;
#pragma unroll
        for (int u = 0; u < 8; u++) {
            float4 v = *(const float4*)&Qg[(long long)r * sq + c0 + u * 4];
            Qs[c0 + u*4 + 0][r] = v.x;
            Qs[c0 + u*4 + 1][r] = v.y;
            Qs[c0 + u*4 + 2][r] = v.z;
            Qs[c0 + u*4 + 3][r] = v.w;
        }
    }

    float O[8][4];
#pragma unroll
    for (int i = 0; i < 8; i++)
#pragma unroll
        for (int j = 0; j < 4; j++) O[i][j] = 0.f;
    float m[8], l[8];
#pragma unroll
    for (int i = 0; i < 8; i++) { m[i] = -1e30f; l[i] = 0.f; }

    for (int k0 = 0; k0 < q0 + 128; k0 += 64) {
        __syncthreads();
        {
            int r = tid >> 2;
            int c0 = (tid & 3) * 16;
#pragma unroll
            for (int u = 0; u < 4; u++) {
                float4 kv = *(const float4*)&Kg[(long long)(k0 + r) * sk + c0 + u * 4];
                Ks[c0 + u*4 + 0][r] = kv.x;
                Ks[c0 + u*4 + 1][r] = kv.y;
                Ks[c0 + u*4 + 2][r] = kv.z;
                Ks[c0 + u*4 + 3][r] = kv.w;
                *(float4*)&Vs[r][c0 + u*4] =
                    *(const float4*)&Vg[(long long)(k0 + r) * sv + c0 + u * 4];
            }
        }
        __syncthreads();

        float s[8][4];
#pragma unroll
        for (int i = 0; i < 8; i++)
#pragma unroll
            for (int j = 0; j < 4; j++) s[i][j] = 0.f;
#pragma unroll 8
        for (int d = 0; d < 64; d++) {
            float a[8], bb[4];
            *(float4*)&a[0] = *(const float4*)&Qs[d][ty * 8];
            *(float4*)&a[4] = *(const float4*)&Qs[d][ty * 8 + 4];
            *(float4*)&bb[0] = *(const float4*)&Ks[d][tx * 4];
#pragma unroll
            for (int i = 0; i < 8; i++)
#pragma unroll
                for (int j = 0; j < 4; j++)
                    s[i][j] += a[i] * bb[j];
        }

        if (k0 + 63 > q0) {
#pragma unroll
            for (int i = 0; i < 8; i++)
#pragma unroll
                for (int j = 0; j < 4; j++)
                    s[i][j] = (k0 + tx*4 + j <= q0 + ty*8 + i) ? s[i][j] * 0.125f : -1e30f;
        } else {
#pragma unroll
            for (int i = 0; i < 8; i++)
#pragma unroll
                for (int j = 0; j < 4; j++) s[i][j] *= 0.125f;
        }

#pragma unroll
        for (int i = 0; i < 8; i++) {
            float mx = fmaxf(fmaxf(s[i][0], s[i][1]), fmaxf(s[i][2], s[i][3]));
#pragma unroll
            for (int off = 1; off < 16; off <<= 1)
                mx = fmaxf(mx, __shfl_xor_sync(0xffffffffu, mx, off));
            float mn = fmaxf(m[i], mx);
            float corr = __expf(m[i] - mn);
            float p0 = __expf(s[i][0] - mn);
            float p1 = __expf(s[i][1] - mn);
            float p2 = __expf(s[i][2] - mn);
            float p3 = __expf(s[i][3] - mn);
            *(float4*)&Ps[ty*8 + i][tx*4] = make_float4(p0, p1, p2, p3);
            float sum = p0 + p1 + p2 + p3;
#pragma unroll
            for (int off = 1; off < 16; off <<= 1)
                sum += __shfl_xor_sync(0xffffffffu, sum, off);
            l[i] = l[i] * corr + sum;
            m[i] = mn;
            O[i][0] *= corr; O[i][1] *= corr; O[i][2] *= corr; O[i][3] *= corr;
        }
        __syncthreads();

#pragma unroll 8
        for (int c = 0; c < 64; c++) {
            float bb[4];
            *(float4*)&bb[0] = *(const float4*)&Vs[c][tx * 4];
#pragma unroll
            for (int i = 0; i < 8; i++) {
                float a = Ps[ty*8 + i][c];
                O[i][0] += a*bb[0]; O[i][1] += a*bb[1];
                O[i][2] += a*bb[2]; O[i][3] += a*bb[3];
            }
        }
    }

    float* Og = Out + (long long)(b * SS + q0) * so + h * HDD;
#pragma unroll
    for (int i = 0; i < 8; i++) {
        float inv = 1.f / l[i];
        float4 o = make_float4(O[i][0]*inv, O[i][1]*inv, O[i][2]*inv, O[i][3]*inv);
        *(float4*)&Og[(long long)(ty*8 + i) * so + tx * 4] = o;
    }
}

// ---------------- gating ----------------
__global__ void gate_kernel(const float* __restrict__ Wg,
                            const float* __restrict__ bias) {
    int t = blockIdx.x;
    int w = threadIdx.x >> 5, lane = threadIdx.x & 31;
    if (w >= NR) return;
    float s = 0.f;
    const float* xr = g_xn2 + (long long)t * DD;
    for (int i = lane; i < DD; i += 32) s += xr[i] * Wg[i * NR + w];
#pragma unroll
    for (int off = 16; off > 0; off >>= 1)
        s += __shfl_down_sync(0xffffffff, s, off);
    if (lane == 0)
        g_aff[t * NR + w] = 1.f / (1.f + __expf(-(s + bias[w])));
}

// ---------------- per-token top-2 ----------------
__global__ void top2_kernel() {
    int t = blockIdx.x * blockDim.x + threadIdx.x;
    if (t >= TT) return;
    float a[NR];
#pragma unroll
    for (int e = 0; e < NR; e++) a[e] = g_aff[t * NR + e];
    int e1 = 0; float b1 = a[0];
#pragma unroll
    for (int e = 1; e < NR; e++) if (a[e] > b1) { b1 = a[e]; e1 = e; }
    int e2 = -1; float b2 = -1.f;
#pragma unroll
    for (int e = 0; e < NR; e++) if (e != e1 && a[e] > b2) { b2 = a[e]; e2 = e; }
    g_top[t] = make_int2(e1, e2);
}

// ---------------- per-expert capacity selection ----------------
__global__ void select_kernel() {
    __shared__ unsigned long long keys[TT];
    int e = blockIdx.x;
    int tid = threadIdx.x;
    for (int i = tid; i < TT; i += 1024) {
        int2 tp = g_top[i];
        unsigned hi;
        if (tp.x == e || tp.y == e) {
            unsigned ev = __float_as_uint(g_aff[i * NR + e]);
            hi = ~ev;
        } else {
            hi = 0xFFFFFFFFu;
        }
        keys[i] = ((unsigned long long)hi << 32) | (unsigned)i;
    }
    __syncthreads();
    for (int ksz = 2; ksz <= TT; ksz <<= 1) {
        for (int j = ksz >> 1; j > 0; j >>= 1) {
            for (int base = tid; base < TT / 2; base += 1024) {
                int i = ((base & ~(j - 1)) << 1) | (base & (j - 1));
                int p = i + j;
                bool up = ((i & ksz) == 0);
                unsigned long long a = keys[i], b2 = keys[p];
                if ((a > b2) == up) { keys[i] = b2; keys[p] = a; }
            }
            __syncthreads();
        }
    }
    for (int c = tid; c < CAP; c += 1024) {
        unsigned long long kk = keys[c];
        int idx = (int)(kk & 0xFFFFFFFFu);
        bool valid = (unsigned)(kk >> 32) != 0xFFFFFFFFu;
        g_selidx[e * CAP + c] = idx;
        g_selw[e * CAP + c] = valid ? g_aff[idx * NR + e] : 0.f;
    }
}

// ---------------- scatter-add ----------------
__global__ void scatter_kernel(float* __restrict__ out) {
    int row = blockIdx.x;
    float w = g_selw[row];
    if (w == 0.f) return;
    int t = g_selidx[row];
    int i = threadIdx.x * 4;
    const float* src = &g_eout[(long long)row * DD + i];
    float* dst = &out[(long long)t * DD + i];
#pragma unroll
    for (int j = 0; j < 4; j++) atomicAdd(dst + j, src[j] * w);
}

// ---------------- host helpers ----------------
static float* sym(const void* s) {
    void* p = nullptr;
    cudaGetSymbolAddress(&p, (const void*)s);
    return (float*)p;
}

static void run_gemm(cudaStream_t st, const float* A, const float* B, float* C,
                     const float* Add, int M, int N, int K, int lda) {
    dim3 grid((N + 127) / 128, (M + 127) / 128);
    sgemm128_kernel<<<grid, 256, 0, st>>>(A, B, C, Add, M, N, K, lda);
}

static void run_tf32(cudaStream_t st, const float* A, const float* B, float* C,
                     const float* Add, const int* Aidx, int M, int N, int K, int batch,
                     long long sA, long long sB, long long sC, int mode) {
    dim3 grid(N / 128, (M + 127) / 128, batch);
    tf32gemm_kernel<<<grid, 256, 0, st>>>(A, B, C, Add, Aidx, M, N, K, sA, sB, sC, mode);
}

#define ATT_SMEM (98304)

// one-time-created stream/event resources (work per call is identical/deterministic)
static cudaStream_t g_s1;
static cudaEvent_t g_eStart, g_eXN, g_ePQ, g_eKV, g_eR, g_eMoE;
static int g_res_init = 0;

extern "C" void kernel_launch(void* const* d_in, const int* in_sizes, int n_in,
                              void* d_out, int out_size) {
    const float* x       = (const float*)d_in[0];
    const float* Wq_lat  = (const float*)d_in[2];
    const float* Wkv_lat = (const float*)d_in[3];
    const float* Wrot_q  = (const float*)d_in[4];
    const float* Wrot_k  = (const float*)d_in[5];
    const float* Wq_up   = (const float*)d_in[6];
    const float* Wk_up   = (const float*)d_in[7];
    const float* Wv_up   = (const float*)d_in[8];
    const float* Wout    = (const float*)d_in[9];
    const float* n1w     = (const float*)d_in[10];
    const float* n2w     = (const float*)d_in[11];
    const float* Ws1     = (const float*)d_in[12];
    const float* Ws2     = (const float*)d_in[13];
    const float* Wr1     = (const float*)d_in[14];
    const float* Wr2     = (const float*)d_in[15];
    const float* Wgate   = (const float*)d_in[16];
    const float* ebias   = (const float*)d_in[17];
    float* out = (float*)d_out;

    float* p_xn   = sym(&g_xn);
    float* p_zq   = sym(&g_zq);
    float* p_zkv  = sym(&g_zkv);
    float* p_wqc  = sym(&g_wqc);
    float* p_wkvc = sym(&g_wkvc);
    float* p_qc   = sym(&g_qc);
    float* p_kvc  = sym(&g_kvc);
    float* p_ao   = sym(&g_ao);
    float* p_x1   = sym(&g_x1);
    float* p_xn2  = sym(&g_xn2);
    float* p_hs   = sym(&g_hs);
    float* p_hr2  = sym(&g_hr2);
    float* p_eo   = sym(&g_eout);
    int*   p_sel  = (int*)sym(&g_selidx);

    if (!g_res_init) {
        cudaFuncSetAttribute(fattn_kernel, cudaFuncAttributeMaxDynamicSharedMemorySize,
                             ATT_SMEM);
        cudaStreamCreateWithFlags(&g_s1, cudaStreamNonBlocking);
        cudaEventCreateWithFlags(&g_eStart, cudaEventDisableTiming);
        cudaEventCreateWithFlags(&g_eXN, cudaEventDisableTiming);
        cudaEventCreateWithFlags(&g_ePQ, cudaEventDisableTiming);
        cudaEventCreateWithFlags(&g_eKV, cudaEventDisableTiming);
        cudaEventCreateWithFlags(&g_eR, cudaEventDisableTiming);
        cudaEventCreateWithFlags(&g_eMoE, cudaEventDisableTiming);
        g_res_init = 1;
    }
    cudaStream_t s0 = 0, s1 = g_s1;

    // fork
    cudaEventRecord(g_eStart, s0);
    cudaStreamWaitEvent(s1, g_eStart, 0);

    // s0: rmsnorm; s1: weight packs (both tiny, concurrent)
    rmsnorm_kernel<<<TT, 256, 0, s0>>>(x, n1w, p_xn);
    cudaEventRecord(g_eXN, s0);
    packq_kernel <<<(LQ * QC + 255) / 256, 256, 0, s1>>>(Wq_up, Wrot_q);
    packkv_kernel<<<(LKV * KVC + 255) / 256, 256, 0, s1>>>(Wk_up, Wv_up, Wrot_k);
    cudaEventRecord(g_ePQ, s1);

    // q chain on s0: zq = xn@Wq_lat -> qc = zq@wqc
    cudaStreamWaitEvent(s0, g_ePQ, 0);
    run_gemm(s0, p_xn, Wq_lat, p_zq, nullptr, TT, LQ, DD, DD);
    run_gemm(s0, p_zq, p_wqc, p_qc, nullptr, TT, QC, LQ, LQ);

    // kv chain on s1: zkv = xn@Wkv_lat -> kvc = zkv@wkvc
    cudaStreamWaitEvent(s1, g_eXN, 0);
    run_gemm(s1, p_xn, Wkv_lat, p_zkv, nullptr, TT, LKV, DD, DD);
    run_gemm(s1, p_zkv, p_wkvc, p_kvc, nullptr, TT, KVC, LKV, LKV);
    cudaEventRecord(g_eKV, s1);
    cudaStreamWaitEvent(s0, g_eKV, 0);

    rope_kernel<<<(TT * HH * ROT + 255) / 256, 256, 0, s0>>>();
    fattn_kernel<<<dim3(SS / 128, TB * HH), 256, ATT_SMEM, s0>>>(
        p_qc, QC, p_kvc, KVC, p_kvc + 1024, KVC, p_ao, DD);
    run_gemm(s0, p_ao, Wout, p_x1, x, TT, DD, DD, DD);
    rmsnorm_kernel<<<TT, 256, 0, s0>>>(p_x1, n2w, p_xn2);
    cudaEventRecord(g_eR, s0);
    cudaStreamWaitEvent(s1, g_eR, 0);

    // routed chain on s1 (gather fused into Wr1 A-loader via selidx)
    gate_kernel<<<TT, 256, 0, s1>>>(Wgate, ebias);
    top2_kernel<<<(TT + 255) / 256, 256, 0, s1>>>();
    select_kernel<<<NR, 1024, 0, s1>>>();
    run_tf32(s1, p_xn2, Wr1, p_hr2, nullptr, p_sel, CAP, 2 * FF, DD, NR,
             0, (long long)DD * 2 * FF, (long long)CAP * FF, 1);
    run_tf32(s1, p_hr2, Wr2, p_eo, nullptr, nullptr, CAP, DD, FF, NR,
             (long long)CAP * FF, (long long)FF * DD, (long long)CAP * DD, 0);
    cudaEventRecord(g_eMoE, s1);

    // shared chain on main: out = x1 + shared (Add-epilogue)
    run_tf32(s0, p_xn2, Ws1, p_hs, nullptr, nullptr, TT, 2 * FF, DD, 1, 0, 0,
             (long long)TT * FF, 1);
    run_tf32(s0, p_hs, Ws2, out, p_x1, nullptr, TT, DD, FF, 1, 0, 0, 0, 0);

    // join: scatter routed experts into out
    cudaStreamWaitEvent(s0, g_eMoE, 0);
    scatter_kernel<<<NR * CAP, 256, 0, s0>>>(out);
}

// round 17
// speedup vs baseline: 1.0488x; 1.0288x over previous
#include <cuda_runtime.h>
#include <cuda_bf16.h>
#include <math.h>

// ---------------- static config ----------------
#define TB 2
#define SS 2048
#define DD 1024
#define HH 16
#define HDD 64
#define ROT 32
#define LQ 512
#define LKV 256
#define FF 1024
#define NR 7
#define CAP 585
#define TT (TB*SS)   // 4096 tokens

#define QC 1536      // q-side concat width: Wq_up(1024) | rot(512)
#define KVC 2560     // kv-side concat width: Wk_up(1024) | Wv_up(1024) | rot(512)

// ---------------- device scratch ----------------
__device__ float g_xn [TT*DD];
__device__ float g_zq [TT*LQ];
__device__ float g_zkv[TT*LKV];
__device__ float g_wqc [LQ*QC];     // Wq_up || packed rot q
__device__ float g_wkvc[LKV*KVC];   // Wk_up || Wv_up || packed rot k
__device__ float g_qc [TT*QC];
__device__ float g_kvc[TT*KVC];
__device__ float g_ao [TT*DD];
__device__ float g_x1 [TT*DD];
__device__ float g_xn2[TT*DD];
__device__ float g_hs [TT*FF];
__device__ float g_aff[TT*NR];
__device__ int2  g_top[TT];
__device__ int   g_selidx[NR*CAP];
__device__ float g_selw  [NR*CAP];
__device__ float g_hr2 [NR*CAP*FF];
__device__ float g_eout[NR*CAP*DD];

// ---------------- helpers ----------------
__device__ __forceinline__ unsigned f2tf32(float f) {
    unsigned u;
    asm("cvt.rna.tf32.f32 %0, %1;" : "=r"(u) : "f"(f));
    return u;
}

__device__ __forceinline__ void mma_tf32(float* c, const unsigned* a, const unsigned* b) {
    asm volatile(
        "mma.sync.aligned.m16n8k8.row.col.f32.tf32.tf32.f32 "
        "{%0,%1,%2,%3}, {%4,%5,%6,%7}, {%8,%9}, {%0,%1,%2,%3};"
        : "+f"(c[0]), "+f"(c[1]), "+f"(c[2]), "+f"(c[3])
        : "r"(a[0]), "r"(a[1]), "r"(a[2]), "r"(a[3]), "r"(b[0]), "r"(b[1]));
}

// ---------------- RMSNorm ----------------
__global__ void rmsnorm_kernel(const float* __restrict__ x,
                               const float* __restrict__ w,
                               float* __restrict__ o) {
    int t = blockIdx.x;
    int tid = threadIdx.x;
    __shared__ float red[256];
    const float4* xr = (const float4*)(x + (long long)t * DD);
    float4 v = xr[tid];
    float ss = v.x*v.x + v.y*v.y + v.z*v.z + v.w*v.w;
    red[tid] = ss; __syncthreads();
    for (int off = 128; off > 0; off >>= 1) {
        if (tid < off) red[tid] += red[tid + off];
        __syncthreads();
    }
    float inv = rsqrtf(red[0] / (float)DD + 1e-6f);
    const float4* wr = (const float4*)w;
    float4 wv = wr[tid];
    float4 ov = make_float4(v.x*inv*wv.x, v.y*inv*wv.y, v.z*inv*wv.z, v.w*inv*wv.w);
    ((float4*)(o + (long long)t * DD))[tid] = ov;
}

// ---------------- fused RMSNorm2 + gate + top2 ----------------
// One block per token: normalize row -> xn2 (and smem), gate dots from smem,
// sigmoid affinities + per-token top-2.
__global__ void rmsgate_kernel(const float* __restrict__ x,
                               const float* __restrict__ w,
                               float* __restrict__ o,
                               const float* __restrict__ Wg,
                               const float* __restrict__ bias) {
    int t = blockIdx.x;
    int tid = threadIdx.x;
    __shared__ float red[256];
    __shared__ __align__(16) float xs[DD];
    __shared__ float affs[NR];

    const float4* xr = (const float4*)(x + (long long)t * DD);
    float4 v = xr[tid];
    float ss = v.x*v.x + v.y*v.y + v.z*v.z + v.w*v.w;
    red[tid] = ss; __syncthreads();
    for (int off = 128; off > 0; off >>= 1) {
        if (tid < off) red[tid] += red[tid + off];
        __syncthreads();
    }
    float inv = rsqrtf(red[0] / (float)DD + 1e-6f);
    const float4* wr = (const float4*)w;
    float4 wv = wr[tid];
    float4 ov = make_float4(v.x*inv*wv.x, v.y*inv*wv.y, v.z*inv*wv.z, v.w*inv*wv.w);
    ((float4*)(o + (long long)t * DD))[tid] = ov;
    *(float4*)&xs[tid * 4] = ov;
    __syncthreads();

    // gate: warp w computes expert w's dot over the normalized row
    int wid = tid >> 5, lane = tid & 31;
    if (wid < NR) {
        float s = 0.f;
        for (int i = lane; i < DD; i += 32) s += xs[i] * Wg[i * NR + wid];
#pragma unroll
        for (int off = 16; off > 0; off >>= 1)
            s += __shfl_down_sync(0xffffffff, s, off);
        if (lane == 0) {
            float a = 1.f / (1.f + __expf(-(s + bias[wid])));
            g_aff[t * NR + wid] = a;
            affs[wid] = a;
        }
    }
    __syncthreads();

    if (tid == 0) {
        float a[NR];
#pragma unroll
        for (int e = 0; e < NR; e++) a[e] = affs[e];
        int e1 = 0; float b1 = a[0];
#pragma unroll
        for (int e = 1; e < NR; e++) if (a[e] > b1) { b1 = a[e]; e1 = e; }
        int e2 = -1; float b2 = -1.f;
#pragma unroll
        for (int e = 0; e < NR; e++) if (e != e1 && a[e] > b2) { b2 = a[e]; e2 = e; }
        g_top[t] = make_int2(e1, e2);
    }
}

// ---------------- SGEMM 128x128x16, 8x8 micro-tile, double-buffered (fp32) ----------------
__global__ void __launch_bounds__(256)
sgemm128_kernel(const float* __restrict__ A,
                const float* __restrict__ B,
                float* __restrict__ C,
                const float* __restrict__ Add,
                int M, int N, int K, int lda) {
    int m0 = blockIdx.y * 128, n0 = blockIdx.x * 128;
    int tid = threadIdx.x;
    int ty = tid >> 4, tx = tid & 15;

    __shared__ __align__(16) float As[2][16][128];
    __shared__ __align__(16) float Bs[2][16][128];

    float acc[8][8];
#pragma unroll
    for (int i = 0; i < 8; i++)
#pragma unroll
        for (int j = 0; j < 8; j++) acc[i][j] = 0.f;

    int arow = tid >> 1;
    int acol = (tid & 1) * 8;
    int brow = tid >> 4;
    int bcol = (tid & 15) * 8;
    bool arowok = (m0 + arow) < M;
    const float* Ap = A + (long long)(m0 + arow) * lda + acol;
    const float* Bp = B + (long long)brow * N + n0 + bcol;

    float4 av0 = make_float4(0,0,0,0), av1 = av0, bv0, bv1;
    if (arowok) {
        av0 = *(const float4*)&Ap[0];
        av1 = *(const float4*)&Ap[4];
    }
    bv0 = *(const float4*)&Bp[0];
    bv1 = *(const float4*)&Bp[4];

    {
        As[0][acol + 0][arow] = av0.x; As[0][acol + 1][arow] = av0.y;
        As[0][acol + 2][arow] = av0.z; As[0][acol + 3][arow] = av0.w;
        As[0][acol + 4][arow] = av1.x; As[0][acol + 5][arow] = av1.y;
        As[0][acol + 6][arow] = av1.z; As[0][acol + 7][arow] = av1.w;
        *(float4*)&Bs[0][brow][bcol] = bv0;
        *(float4*)&Bs[0][brow][bcol + 4] = bv1;
    }
    __syncthreads();

    int nk = K >> 4;
    for (int t = 0; t < nk; t++) {
        int cur = t & 1;
        if (t + 1 < nk) {
            const float* Apn = Ap + (t + 1) * 16;
            const float* Bpn = Bp + (long long)(t + 1) * 16 * N;
            if (arowok) {
                av0 = *(const float4*)&Apn[0];
                av1 = *(const float4*)&Apn[4];
            }
            bv0 = *(const float4*)&Bpn[0];
            bv1 = *(const float4*)&Bpn[4];
        }
#pragma unroll
        for (int kk = 0; kk < 16; kk++) {
            float a[8], b[8];
            *(float4*)&a[0] = *(const float4*)&As[cur][kk][ty * 4];
            *(float4*)&a[4] = *(const float4*)&As[cur][kk][64 + ty * 4];
            *(float4*)&b[0] = *(const float4*)&Bs[cur][kk][tx * 4];
            *(float4*)&b[4] = *(const float4*)&Bs[cur][kk][64 + tx * 4];
#pragma unroll
            for (int i = 0; i < 8; i++)
#pragma unroll
                for (int j = 0; j < 8; j++)
                    acc[i][j] += a[i] * b[j];
        }
        if (t + 1 < nk) {
            int nxt = cur ^ 1;
            As[nxt][acol + 0][arow] = av0.x; As[nxt][acol + 1][arow] = av0.y;
            As[nxt][acol + 2][arow] = av0.z; As[nxt][acol + 3][arow] = av0.w;
            As[nxt][acol + 4][arow] = av1.x; As[nxt][acol + 5][arow] = av1.y;
            As[nxt][acol + 6][arow] = av1.z; As[nxt][acol + 7][arow] = av1.w;
            *(float4*)&Bs[nxt][brow][bcol] = bv0;
            *(float4*)&Bs[nxt][brow][bcol + 4] = bv1;
        }
        __syncthreads();
    }

#pragma unroll
    for (int hi = 0; hi < 2; hi++) {
#pragma unroll
        for (int ii = 0; ii < 4; ii++) {
            int row = m0 + hi * 64 + ty * 4 + ii;
            if (row >= M) continue;
#pragma unroll
            for (int hj = 0; hj < 2; hj++) {
                long long off = (long long)row * N + n0 + hj * 64 + tx * 4;
                int ai = hi * 4 + ii;
                float4 r = make_float4(acc[ai][hj*4+0], acc[ai][hj*4+1],
                                       acc[ai][hj*4+2], acc[ai][hj*4+3]);
                if (Add) {
                    float4 ad = *(const float4*)&Add[off];
                    r.x += ad.x; r.y += ad.y; r.z += ad.z; r.w += ad.w;
                }
                *(float4*)&C[off] = r;
            }
        }
    }
}

// ---------------- TF32 tensor-core GEMM 128x128x16 (MoE path) ----------------
// mode 0: C = acc (+Add), B plain.
// mode 1: fused SwiGLU; B halves (a|b) interleaved on the fly; C[M x N/2] = a*silu(b).
// Aidx: optional per-row gather index (row -> Aidx[z*M+row] into A); A not z-offset.
__global__ void __launch_bounds__(256)
tf32gemm_kernel(const float* __restrict__ A,
                const float* __restrict__ B,
                float* __restrict__ C,
                const float* __restrict__ Add,
                const int* __restrict__ Aidx,
                int M, int N, int K,
                long long sA, long long sB, long long sC, int mode) {
    int z = blockIdx.z;
    A += (long long)z * sA;
    B += (long long)z * sB;
    C += (long long)z * sC;
    if (Add) Add += (long long)z * sC;

    const int m0 = blockIdx.y * 128, n0 = blockIdx.x * 128;
    const int tid = threadIdx.x;
    const int w = tid >> 5, lane = tid & 31;
    const int wm = (w >> 2) * 64;
    const int wn = (w & 3) * 32;
    const int gr = lane >> 2, c4 = lane & 3;

    __shared__ float As[2][16][136];
    __shared__ float Bs[2][16][136];

    float acc[4][4][4];
#pragma unroll
    for (int i = 0; i < 4; i++)
#pragma unroll
        for (int j = 0; j < 4; j++)
#pragma unroll
            for (int r = 0; r < 4; r++) acc[i][j][r] = 0.f;

    const int arow = tid >> 1;
    const int acol = (tid & 1) * 8;
    const int brow = tid >> 4;
    const int bcol = (tid & 15) * 8;
    const bool arowok = (m0 + arow) < M;
    long long arow_g = m0 + arow;
    if (Aidx && arowok) arow_g = Aidx[(long long)z * M + m0 + arow];
    const float* Ap = A + arow_g * K + acol;
    const float* BpA;
    const float* BpB = nullptr;
    if (mode == 1) {
        BpA = B + (long long)brow * N + (n0 >> 1) + (bcol >> 1);
        BpB = BpA + FF;
    } else {
        BpA = B + (long long)brow * N + n0 + bcol;
    }

    float ar[8], br[8];
#pragma unroll
    for (int j = 0; j < 8; j++) ar[j] = 0.f;
    if (arowok) {
        float4 a0 = *(const float4*)&Ap[0];
        float4 a1 = *(const float4*)&Ap[4];
        ar[0]=a0.x; ar[1]=a0.y; ar[2]=a0.z; ar[3]=a0.w;
        ar[4]=a1.x; ar[5]=a1.y; ar[6]=a1.z; ar[7]=a1.w;
    }
    {
        float4 b0 = *(const float4*)&BpA[0];
        float4 b1 = (mode == 1) ? *(const float4*)&BpB[0]
                                : *(const float4*)&BpA[4];
        br[0]=b0.x; br[1]=b0.y; br[2]=b0.z; br[3]=b0.w;
        br[4]=b1.x; br[5]=b1.y; br[6]=b1.z; br[7]=b1.w;
    }
#pragma unroll
    for (int j = 0; j < 8; j++)
        As[0][acol + j][arow] = __uint_as_float(f2tf32(ar[j]));
    if (mode == 1) {
#pragma unroll
        for (int i = 0; i < 4; i++) {
            Bs[0][brow][bcol + 2*i]     = __uint_as_float(f2tf32(br[i]));
            Bs[0][brow][bcol + 2*i + 1] = __uint_as_float(f2tf32(br[4 + i]));
        }
    } else {
#pragma unroll
        for (int j = 0; j < 8; j++)
            Bs[0][brow][bcol + j] = __uint_as_float(f2tf32(br[j]));
    }
    __syncthreads();

    const int nk = K >> 4;
    for (int t = 0; t < nk; t++) {
        int cur = t & 1;
        if (t + 1 < nk) {
            const float* Apn = Ap + (t + 1) * 16;
            long long boff = (long long)(t + 1) * 16 * N;
            if (arowok) {
                float4 a0 = *(const float4*)&Apn[0];
                float4 a1 = *(const float4*)&Apn[4];
                ar[0]=a0.x; ar[1]=a0.y; ar[2]=a0.z; ar[3]=a0.w;
                ar[4]=a1.x; ar[5]=a1.y; ar[6]=a1.z; ar[7]=a1.w;
            }
            float4 b0 = *(const float4*)&BpA[boff];
            float4 b1 = (mode == 1) ? *(const float4*)&BpB[boff]
                                    : *(const float4*)&BpA[boff + 4];
            br[0]=b0.x; br[1]=b0.y; br[2]=b0.z; br[3]=b0.w;
            br[4]=b1.x; br[5]=b1.y; br[6]=b1.z; br[7]=b1.w;
        }
#pragma unroll
        for (int ks = 0; ks < 16; ks += 8) {
            unsigned af[4][4], bf[4][2];
#pragma unroll
            for (int mf = 0; mf < 4; mf++) {
                int am = wm + mf * 16;
                af[mf][0] = __float_as_uint(As[cur][ks + c4    ][am + gr    ]);
                af[mf][1] = __float_as_uint(As[cur][ks + c4    ][am + gr + 8]);
                af[mf][2] = __float_as_uint(As[cur][ks + c4 + 4][am + gr    ]);
                af[mf][3] = __float_as_uint(As[cur][ks + c4 + 4][am + gr + 8]);
            }
#pragma unroll
            for (int nf = 0; nf < 4; nf++) {
                int bn = wn + nf * 8;
                bf[nf][0] = __float_as_uint(Bs[cur][ks + c4    ][bn + gr]);
                bf[nf][1] = __float_as_uint(Bs[cur][ks + c4 + 4][bn + gr]);
            }
#pragma unroll
            for (int mf = 0; mf < 4; mf++)
#pragma unroll
                for (int nf = 0; nf < 4; nf++)
                    mma_tf32(acc[mf][nf], af[mf], bf[nf]);
        }
        if (t + 1 < nk) {
            int nxt = cur ^ 1;
#pragma unroll
            for (int j = 0; j < 8; j++)
                As[nxt][acol + j][arow] = __uint_as_float(f2tf32(ar[j]));
            if (mode == 1) {
#pragma unroll
                for (int i = 0; i < 4; i++) {
                    Bs[nxt][brow][bcol + 2*i]     = __uint_as_float(f2tf32(br[i]));
                    Bs[nxt][brow][bcol + 2*i + 1] = __uint_as_float(f2tf32(br[4 + i]));
                }
            } else {
#pragma unroll
                for (int j = 0; j < 8; j++)
                    Bs[nxt][brow][bcol + j] = __uint_as_float(f2tf32(br[j]));
            }
        }
        __syncthreads();
    }

#pragma unroll
    for (int mf = 0; mf < 4; mf++) {
        int rr[2];
        rr[0] = m0 + wm + mf * 16 + gr;
        rr[1] = rr[0] + 8;
#pragma unroll
        for (int nf = 0; nf < 4; nf++) {
            int col = n0 + wn + nf * 8 + c4 * 2;
#pragma unroll
            for (int half = 0; half < 2; half++) {
                int row = rr[half];
                if (row >= M) continue;
                float2 v = make_float2(acc[mf][nf][half*2], acc[mf][nf][half*2+1]);
                if (mode == 0) {
                    if (Add) {
                        float2 ad = *(const float2*)&Add[(long long)row * N + col];
                        v.x += ad.x; v.y += ad.y;
                    }
                    *(float2*)&C[(long long)row * N + col] = v;
                } else {
                    float sw = v.x * (v.y / (1.f + __expf(-v.y)));
                    C[(long long)row * (N >> 1) + (col >> 1)] = sw;
                }
            }
        }
    }
}

// ---------------- weight pack kernels ----------------
__global__ void packq_kernel(const float* __restrict__ Wq_up,
                             const float* __restrict__ Wrot_q) {
    int idx = blockIdx.x * 256 + threadIdx.x;
    if (idx >= LQ * QC) return;
    int r = idx / QC, c = idx % QC;
    if (c < 1024) {
        g_wqc[idx] = Wq_up[r * 1024 + c];
    } else {
        int cc = c - 1024, h = cc >> 5, j = cc & 31;
        g_wqc[idx] = Wrot_q[r * 1024 + h * 64 + j];
    }
}

__global__ void packkv_kernel(const float* __restrict__ Wk_up,
                              const float* __restrict__ Wv_up,
                              const float* __restrict__ Wrot_k) {
    int idx = blockIdx.x * 256 + threadIdx.x;
    if (idx >= LKV * KVC) return;
    int r = idx / KVC, c = idx % KVC;
    if (c < 1024) {
        g_wkvc[idx] = Wk_up[r * 1024 + c];
    } else if (c < 2048) {
        g_wkvc[idx] = Wv_up[r * 1024 + (c - 1024)];
    } else {
        int cc = c - 2048, h = cc >> 5, j = cc & 31;
        g_wkvc[idx] = Wrot_k[r * 1024 + h * 64 + j];
    }
}

// ---------------- RoPE ----------------
__global__ void rope_kernel() {
    int idx = blockIdx.x * blockDim.x + threadIdx.x;
    if (idx >= TT * HH * ROT) return;
    int j = idx & (ROT - 1);
    int h = (idx >> 5) & (HH - 1);
    int t = idx >> 9;
    int s = t & (SS - 1);
    int i = j & 15;
    float invf = __expf(-9.210340371976184f * (float)i / 16.f);
    float ang = (float)s * invf;
    float sn, c;
    sincosf(ang, &sn, &c);
    long long qb = (long long)t * QC + 1024 + h * 32;
    long long kb = (long long)t * KVC + 2048 + h * 32;
    float qr = g_qc[qb + j];
    float kr = g_kvc[kb + j];
    float qo = (j < 16) ? -g_qc[qb + j + 16] : g_qc[qb + j - 16];
    float ko = (j < 16) ? -g_kvc[kb + j + 16] : g_kvc[kb + j - 16];
    g_qc [(long long)t * QC  + h * HDD + 32 + j] = qr * c + qo * sn;
    g_kvc[(long long)t * KVC + h * HDD + 32 + j] = kr * c + ko * sn;
}

// ---------------- flash attention: 128 q x 64 k, 8x4 micro ----------------
__global__ void __launch_bounds__(256)
fattn_kernel(const float* __restrict__ Q, int sq,
             const float* __restrict__ K, int sk,
             const float* __restrict__ V, int sv,
             float* __restrict__ Out, int so) {
    extern __shared__ float sm[];
    float (*Qs)[128] = (float(*)[128])sm;
    float (*Ks)[64]  = (float(*)[64])(sm + 64 * 128);
    float (*Vs)[64]  = (float(*)[64])(sm + 64 * 128 + 64 * 64);
    float (*Ps)[64]  = (float(*)[64])(sm + 64 * 128 + 2 * 64 * 64);

    const int q0 = blockIdx.x * 128;
    const int bh = blockIdx.y;
    const int b = bh >> 4, h = bh & 15;
    const int tid = threadIdx.x;
    const int ty = tid >> 4, tx = tid & 15;

    const float* Qg = Q + (long long)(b * SS + q0) * sq + h * HDD;
    const float* Kg = K + (long long)b * SS * sk + h * HDD;
    const float* Vg = V + (long long)b * SS * sv + h * HDD;

    {
        int r = tid >> 1;
        int c0 = (tid & 1) * 32;
#pragma unroll
        for (int u = 0; u < 8; u++) {
            float4 v = *(const float4*)&Qg[(long long)r * sq + c0 + u * 4];
            Qs[c0 + u*4 + 0][r] = v.x;
            Qs[c0 + u*4 + 1][r] = v.y;
            Qs[c0 + u*4 + 2][r] = v.z;
            Qs[c0 + u*4 + 3][r] = v.w;
        }
    }

    float O[8][4];
#pragma unroll
    for (int i = 0; i < 8; i++)
#pragma unroll
        for (int j = 0; j < 4; j++) O[i][j] = 0.f;
    float m[8], l[8];
#pragma unroll
    for (int i = 0; i < 8; i++) { m[i] = -1e30f; l[i] = 0.f; }

    for (int k0 = 0; k0 < q0 + 128; k0 += 64) {
        __syncthreads();
        {
            int r = tid >> 2;
            int c0 = (tid & 3) * 16;
#pragma unroll
            for (int u = 0; u < 4; u++) {
                float4 kv = *(const float4*)&Kg[(long long)(k0 + r) * sk + c0 + u * 4];
                Ks[c0 + u*4 + 0][r] = kv.x;
                Ks[c0 + u*4 + 1][r] = kv.y;
                Ks[c0 + u*4 + 2][r] = kv.z;
                Ks[c0 + u*4 + 3][r] = kv.w;
                *(float4*)&Vs[r][c0 + u*4] =
                    *(const float4*)&Vg[(long long)(k0 + r) * sv + c0 + u * 4];
            }
        }
        __syncthreads();

        float s[8][4];
#pragma unroll
        for (int i = 0; i < 8; i++)
#pragma unroll
            for (int j = 0; j < 4; j++) s[i][j] = 0.f;
#pragma unroll 8
        for (int d = 0; d < 64; d++) {
            float a[8], bb[4];
            *(float4*)&a[0] = *(const float4*)&Qs[d][ty * 8];
            *(float4*)&a[4] = *(const float4*)&Qs[d][ty * 8 + 4];
            *(float4*)&bb[0] = *(const float4*)&Ks[d][tx * 4];
#pragma unroll
            for (int i = 0; i < 8; i++)
#pragma unroll
                for (int j = 0; j < 4; j++)
                    s[i][j] += a[i] * bb[j];
        }

        if (k0 + 63 > q0) {
#pragma unroll
            for (int i = 0; i < 8; i++)
#pragma unroll
                for (int j = 0; j < 4; j++)
                    s[i][j] = (k0 + tx*4 + j <= q0 + ty*8 + i) ? s[i][j] * 0.125f : -1e30f;
        } else {
#pragma unroll
            for (int i = 0; i < 8; i++)
#pragma unroll
                for (int j = 0; j < 4; j++) s[i][j] *= 0.125f;
        }

#pragma unroll
        for (int i = 0; i < 8; i++) {
            float mx = fmaxf(fmaxf(s[i][0], s[i][1]), fmaxf(s[i][2], s[i][3]));
#pragma unroll
            for (int off = 1; off < 16; off <<= 1)
                mx = fmaxf(mx, __shfl_xor_sync(0xffffffffu, mx, off));
            float mn = fmaxf(m[i], mx);
            float corr = __expf(m[i] - mn);
            float p0 = __expf(s[i][0] - mn);
            float p1 = __expf(s[i][1] - mn);
            float p2 = __expf(s[i][2] - mn);
            float p3 = __expf(s[i][3] - mn);
            *(float4*)&Ps[ty*8 + i][tx*4] = make_float4(p0, p1, p2, p3);
            float sum = p0 + p1 + p2 + p3;
#pragma unroll
            for (int off = 1; off < 16; off <<= 1)
                sum += __shfl_xor_sync(0xffffffffu, sum, off);
            l[i] = l[i] * corr + sum;
            m[i] = mn;
            O[i][0] *= corr; O[i][1] *= corr; O[i][2] *= corr; O[i][3] *= corr;
        }
        __syncthreads();

#pragma unroll 8
        for (int c = 0; c < 64; c++) {
            float bb[4];
            *(float4*)&bb[0] = *(const float4*)&Vs[c][tx * 4];
#pragma unroll
            for (int i = 0; i < 8; i++) {
                float a = Ps[ty*8 + i][c];
                O[i][0] += a*bb[0]; O[i][1] += a*bb[1];
                O[i][2] += a*bb[2]; O[i][3] += a*bb[3];
            }
        }
    }

    float* Og = Out + (long long)(b * SS + q0) * so + h * HDD;
#pragma unroll
    for (int i = 0; i < 8; i++) {
        float inv = 1.f / l[i];
        float4 o = make_float4(O[i][0]*inv, O[i][1]*inv, O[i][2]*inv, O[i][3]*inv);
        *(float4*)&Og[(long long)(ty*8 + i) * so + tx * 4] = o;
    }
}

// ---------------- per-expert capacity selection ----------------
__global__ void select_kernel() {
    __shared__ unsigned long long keys[TT];
    int e = blockIdx.x;
    int tid = threadIdx.x;
    for (int i = tid; i < TT; i += 1024) {
        int2 tp = g_top[i];
        unsigned hi;
        if (tp.x == e || tp.y == e) {
            unsigned ev = __float_as_uint(g_aff[i * NR + e]);
            hi = ~ev;
        } else {
            hi = 0xFFFFFFFFu;
        }
        keys[i] = ((unsigned long long)hi << 32) | (unsigned)i;
    }
    __syncthreads();
    for (int ksz = 2; ksz <= TT; ksz <<= 1) {
        for (int j = ksz >> 1; j > 0; j >>= 1) {
            for (int base = tid; base < TT / 2; base += 1024) {
                int i = ((base & ~(j - 1)) << 1) | (base & (j - 1));
                int p = i + j;
                bool up = ((i & ksz) == 0);
                unsigned long long a = keys[i], b2 = keys[p];
                if ((a > b2) == up) { keys[i] = b2; keys[p] = a; }
            }
            __syncthreads();
        }
    }
    for (int c = tid; c < CAP; c += 1024) {
        unsigned long long kk = keys[c];
        int idx = (int)(kk & 0xFFFFFFFFu);
        bool valid = (unsigned)(kk >> 32) != 0xFFFFFFFFu;
        g_selidx[e * CAP + c] = idx;
        g_selw[e * CAP + c] = valid ? g_aff[idx * NR + e] : 0.f;
    }
}

// ---------------- scatter-add ----------------
__global__ void scatter_kernel(float* __restrict__ out) {
    int row = blockIdx.x;
    float w = g_selw[row];
    if (w == 0.f) return;
    int t = g_selidx[row];
    int i = threadIdx.x * 4;
    const float* src = &g_eout[(long long)row * DD + i];
    float* dst = &out[(long long)t * DD + i];
#pragma unroll
    for (int j = 0; j < 4; j++) atomicAdd(dst + j, src[j] * w);
}

// ---------------- host helpers ----------------
static float* sym(const void* s) {
    void* p = nullptr;
    cudaGetSymbolAddress(&p, (const void*)s);
    return (float*)p;
}

static void run_gemm(cudaStream_t st, const float* A, const float* B, float* C,
                     const float* Add, int M, int N, int K, int lda) {
    dim3 grid((N + 127) / 128, (M + 127) / 128);
    sgemm128_kernel<<<grid, 256, 0, st>>>(A, B, C, Add, M, N, K, lda);
}

static void run_tf32(cudaStream_t st, const float* A, const float* B, float* C,
                     const float* Add, const int* Aidx, int M, int N, int K, int batch,
                     long long sA, long long sB, long long sC, int mode) {
    dim3 grid(N / 128, (M + 127) / 128, batch);
    tf32gemm_kernel<<<grid, 256, 0, st>>>(A, B, C, Add, Aidx, M, N, K, sA, sB, sC, mode);
}

#define ATT_SMEM (98304)

// one-time-created stream/event resources (work per call is identical/deterministic)
static cudaStream_t g_s1;
static cudaEvent_t g_eStart, g_eXN, g_ePQ, g_eKV, g_eR, g_eMoE;
static int g_res_init = 0;

extern "C" void kernel_launch(void* const* d_in, const int* in_sizes, int n_in,
                              void* d_out, int out_size) {
    const float* x       = (const float*)d_in[0];
    const float* Wq_lat  = (const float*)d_in[2];
    const float* Wkv_lat = (const float*)d_in[3];
    const float* Wrot_q  = (const float*)d_in[4];
    const float* Wrot_k  = (const float*)d_in[5];
    const float* Wq_up   = (const float*)d_in[6];
    const float* Wk_up   = (const float*)d_in[7];
    const float* Wv_up   = (const float*)d_in[8];
    const float* Wout    = (const float*)d_in[9];
    const float* n1w     = (const float*)d_in[10];
    const float* n2w     = (const float*)d_in[11];
    const float* Ws1     = (const float*)d_in[12];
    const float* Ws2     = (const float*)d_in[13];
    const float* Wr1     = (const float*)d_in[14];
    const float* Wr2     = (const float*)d_in[15];
    const float* Wgate   = (const float*)d_in[16];
    const float* ebias   = (const float*)d_in[17];
    float* out = (float*)d_out;

    float* p_xn   = sym(&g_xn);
    float* p_zq   = sym(&g_zq);
    float* p_zkv  = sym(&g_zkv);
    float* p_wqc  = sym(&g_wqc);
    float* p_wkvc = sym(&g_wkvc);
    float* p_qc   = sym(&g_qc);
    float* p_kvc  = sym(&g_kvc);
    float* p_ao   = sym(&g_ao);
    float* p_x1   = sym(&g_x1);
    float* p_xn2  = sym(&g_xn2);
    float* p_hs   = sym(&g_hs);
    float* p_hr2  = sym(&g_hr2);
    float* p_eo   = sym(&g_eout);
    int*   p_sel  = (int*)sym(&g_selidx);

    if (!g_res_init) {
        cudaFuncSetAttribute(fattn_kernel, cudaFuncAttributeMaxDynamicSharedMemorySize,
                             ATT_SMEM);
        cudaStreamCreateWithFlags(&g_s1, cudaStreamNonBlocking);
        cudaEventCreateWithFlags(&g_eStart, cudaEventDisableTiming);
        cudaEventCreateWithFlags(&g_eXN, cudaEventDisableTiming);
        cudaEventCreateWithFlags(&g_ePQ, cudaEventDisableTiming);
        cudaEventCreateWithFlags(&g_eKV, cudaEventDisableTiming);
        cudaEventCreateWithFlags(&g_eR, cudaEventDisableTiming);
        cudaEventCreateWithFlags(&g_eMoE, cudaEventDisableTiming);
        g_res_init = 1;
    }
    cudaStream_t s0 = 0, s1 = g_s1;

    // fork
    cudaEventRecord(g_eStart, s0);
    cudaStreamWaitEvent(s1, g_eStart, 0);

    // s0: rmsnorm; s1: weight packs (both tiny, concurrent)
    rmsnorm_kernel<<<TT, 256, 0, s0>>>(x, n1w, p_xn);
    cudaEventRecord(g_eXN, s0);
    packq_kernel <<<(LQ * QC + 255) / 256, 256, 0, s1>>>(Wq_up, Wrot_q);
    packkv_kernel<<<(LKV * KVC + 255) / 256, 256, 0, s1>>>(Wk_up, Wv_up, Wrot_k);
    cudaEventRecord(g_ePQ, s1);

    // q chain on s0: zq = xn@Wq_lat -> qc = zq@wqc
    cudaStreamWaitEvent(s0, g_ePQ, 0);
    run_gemm(s0, p_xn, Wq_lat, p_zq, nullptr, TT, LQ, DD, DD);
    run_gemm(s0, p_zq, p_wqc, p_qc, nullptr, TT, QC, LQ, LQ);

    // kv chain on s1: zkv = xn@Wkv_lat -> kvc = zkv@wkvc
    cudaStreamWaitEvent(s1, g_eXN, 0);
    run_gemm(s1, p_xn, Wkv_lat, p_zkv, nullptr, TT, LKV, DD, DD);
    run_gemm(s1, p_zkv, p_wkvc, p_kvc, nullptr, TT, KVC, LKV, LKV);
    cudaEventRecord(g_eKV, s1);
    cudaStreamWaitEvent(s0, g_eKV, 0);

    rope_kernel<<<(TT * HH * ROT + 255) / 256, 256, 0, s0>>>();
    fattn_kernel<<<dim3(SS / 128, TB * HH), 256, ATT_SMEM, s0>>>(
        p_qc, QC, p_kvc, KVC, p_kvc + 1024, KVC, p_ao, DD);
    run_gemm(s0, p_ao, Wout, p_x1, x, TT, DD, DD, DD);
    // fused rmsnorm2 + gate + top2 (writes xn2, aff, top)
    rmsgate_kernel<<<TT, 256, 0, s0>>>(p_x1, n2w, p_xn2, Wgate, ebias);
    cudaEventRecord(g_eR, s0);
    cudaStreamWaitEvent(s1, g_eR, 0);

    // routed chain on s1 (gather fused into Wr1 A-loader via selidx)
    select_kernel<<<NR, 1024, 0, s1>>>();
    run_tf32(s1, p_xn2, Wr1, p_hr2, nullptr, p_sel, CAP, 2 * FF, DD, NR,
             0, (long long)DD * 2 * FF, (long long)CAP * FF, 1);
    run_tf32(s1, p_hr2, Wr2, p_eo, nullptr, nullptr, CAP, DD, FF, NR,
             (long long)CAP * FF, (long long)FF * DD, (long long)CAP * DD, 0);
    cudaEventRecord(g_eMoE, s1);

    // shared chain on main: out = x1 + shared (Add-epilogue)
    run_tf32(s0, p_xn2, Ws1, p_hs, nullptr, nullptr, TT, 2 * FF, DD, 1, 0, 0,
             (long long)TT * FF, 1);
    run_tf32(s0, p_hs, Ws2, out, p_x1, nullptr, TT, DD, FF, 1, 0, 0, 0, 0);

    // join: scatter routed experts into out
    cudaStreamWaitEvent(s0, g_eMoE, 0);
    scatter_kernel<<<NR * CAP, 256, 0, s0>>>(out);
}